// round 13
// baseline (speedup 1.0000x reference)
#include <cuda_runtime.h>
#include <cuda_bf16.h>
#include <cuda_fp16.h>
#include <cstdint>
#include <math.h>

// ---------------- problem constants ----------------
#define Vv 50257
#define Ee 768
#define NHh 12
#define HDd 64
#define Ll 4
#define Tt 1024
#define Bb 2
#define FFf 3072
#define BT (Bb*Tt)            // 2048 rows

// ---------------- scratch (static, no allocs) ----------------
__device__ float g_x  [BT * Ee];                 // residual stream (fp32)
__device__ float g_qkv[BT * 3*Ee];               // qkv projection (fp32)
__device__ __half g_h [BT*Ee];                   // LN output fp16
__device__ __half g_at[BT*Ee];                   // attn output fp16
__device__ __half g_f [BT*FFf];                  // ffn hidden fp16
// weights, single fp16
__device__ __half g_qw[Ll*3*Ee*Ee];
__device__ __half g_ow[Ll*Ee*Ee];
__device__ __half g_f1[Ll*FFf*Ee];
__device__ __half g_f2[Ll*Ee*FFf];
__device__ __half g_te[Vv*Ee];

__device__ __forceinline__ uint32_t smem_u32(const void* p) {
    uint32_t a;
    asm("{ .reg .u64 t; cvta.to.shared.u64 t, %1; cvt.u32.u64 %0, t; }" : "=r"(a) : "l"(p));
    return a;
}
__device__ __forceinline__ void cp16(uint32_t dst, const void* src) {
    asm volatile("cp.async.cg.shared.global [%0], [%1], 16;" :: "r"(dst), "l"(src));
}
#define CP_COMMIT() asm volatile("cp.async.commit_group;" ::: "memory")
template<int N> __device__ __forceinline__ void cp_wait() {
    asm volatile("cp.async.wait_group %0;" :: "n"(N) : "memory");
}

__device__ __forceinline__ void ldsm_x4(uint32_t a, uint32_t& r0, uint32_t& r1, uint32_t& r2, uint32_t& r3) {
    asm volatile("ldmatrix.sync.aligned.m8n8.x4.shared.b16 {%0,%1,%2,%3}, [%4];"
                 : "=r"(r0), "=r"(r1), "=r"(r2), "=r"(r3) : "r"(a));
}
__device__ __forceinline__ void mma16816f(float* d, const uint32_t* a, const uint32_t* b) {
    asm volatile("mma.sync.aligned.m16n8k16.row.col.f32.f16.f16.f32 "
                 "{%0,%1,%2,%3}, {%4,%5,%6,%7}, {%8,%9}, {%0,%1,%2,%3};"
                 : "+f"(d[0]), "+f"(d[1]), "+f"(d[2]), "+f"(d[3])
                 : "r"(a[0]), "r"(a[1]), "r"(a[2]), "r"(a[3]), "r"(b[0]), "r"(b[1]));
}

// ---------------- merged fp32 -> fp16 weight conversion (one launch) ----------------
#define C_QW (Ll*3*Ee*Ee/4)
#define C_OW (Ll*Ee*Ee/4)
#define C_F1 (Ll*FFf*Ee/4)
#define C_F2 (Ll*Ee*FFf/4)
#define C_TE (Vv*Ee/4)
#define C_TOT (C_QW + C_OW + C_F1 + C_F2 + C_TE)

__global__ void conv_all_kernel(const float* __restrict__ qkv_w, const float* __restrict__ out_w,
                                const float* __restrict__ fc1_w, const float* __restrict__ fc2_w,
                                const float* __restrict__ tok_emb,
                                __half* __restrict__ qw, __half* __restrict__ ow,
                                __half* __restrict__ f1, __half* __restrict__ f2,
                                __half* __restrict__ te) {
    int i = blockIdx.x * blockDim.x + threadIdx.x;
    if (i >= C_TOT) return;
    const float* src; __half* dst; int off = i;
    if (off < C_QW)                        { src = qkv_w;  dst = qw; }
    else if ((off -= C_QW) < C_OW)         { src = out_w;  dst = ow; }
    else if ((off -= C_OW) < C_F1)         { src = fc1_w;  dst = f1; }
    else if ((off -= C_F1) < C_F2)         { src = fc2_w;  dst = f2; }
    else      { off -= C_F2;                 src = tok_emb; dst = te; }
    float4 v = ((const float4*)src)[off];
    __half2 a, b;
    a.x = __float2half(v.x); a.y = __float2half(v.y);
    b.x = __float2half(v.z); b.y = __float2half(v.w);
    ((__half2*)dst)[2*off]   = a;
    ((__half2*)dst)[2*off+1] = b;
}

// ---------------- embedding ----------------
__global__ void embed_kernel(const int* __restrict__ ids, const float* __restrict__ tok,
                             const float* __restrict__ pos, float* __restrict__ out) {
    int i = blockIdx.x * blockDim.x + threadIdx.x;
    if (i >= BT * Ee) return;
    int e = i % Ee, row = i / Ee, t = row % Tt;
    out[i] = tok[(size_t)ids[row] * Ee + e] + pos[t * Ee + e];
}

// ---------------- layernorm -> fp16 ----------------
__global__ void ln_kernel(const float* __restrict__ x,
                          const float* __restrict__ scale, const float* __restrict__ bias,
                          __half* __restrict__ o) {
    __shared__ float s1[256], s2[256];
    int row = blockIdx.x, tid = threadIdx.x;
    const float* xr = x + (size_t)row * Ee;
    float sum = 0.f, sq = 0.f;
    for (int c = tid; c < Ee; c += 256) { float v = xr[c]; sum += v; sq += v * v; }
    s1[tid] = sum; s2[tid] = sq; __syncthreads();
    for (int s = 128; s > 0; s >>= 1) {
        if (tid < s) { s1[tid] += s1[tid+s]; s2[tid] += s2[tid+s]; }
        __syncthreads();
    }
    float mean = s1[0] * (1.0f / Ee);
    float var  = s2[0] * (1.0f / Ee) - mean * mean;
    float rstd = rsqrtf(var + 1e-5f);
    for (int c = tid; c < Ee; c += 256) {
        float v = (xr[c] - mean) * rstd * scale[c] + bias[c];
        o[(size_t)row * Ee + c] = __float2half(v);
    }
}

// ---------------- HMMA GEMM: C = epi(A @ W^T), single fp16 product ----------------
// BM=64, BN=128, 8 warps each owning a 64x16 tile; 3 CTAs/SM.
#define FLAG_BIAS 1
#define FLAG_GELU 2
#define FLAG_RES  4
#define FLAG_F16OUT 8

#define A_TILE_B (64 * 80)     // 5120
#define W_TILE_B 10240         // 128 rows x 64B padded to 80B
#define STAGE_B  (A_TILE_B + W_TILE_B)   // 15360
#define NSTAGE 3
#define GEMM_SMEM (NSTAGE * STAGE_B)     // 46080

__global__ __launch_bounds__(256, 3)
void gemm_mma(const __half* __restrict__ A, const __half* __restrict__ W,
              const float* __restrict__ bias, const float* __restrict__ res,
              float* __restrict__ C, __half* __restrict__ Cf,
              int N, int K, int flags) {
    extern __shared__ char smem[];
    const uint32_t sb = smem_u32(smem);
    const int tid  = threadIdx.x;
    const int lane = tid & 31;
    const int wn   = tid >> 5;           // 8 warps across N
    const int bm   = blockIdx.x * 64;
    const int bn   = blockIdx.y * 128;

    float acc[4][2][4];
    #pragma unroll
    for (int i = 0; i < 4; i++)
        #pragma unroll
        for (int j = 0; j < 2; j++)
            #pragma unroll
            for (int r = 0; r < 4; r++) acc[i][j][r] = 0.f;

    const int nc = K >> 5;   // BK = 32

    auto load_stage = [&](int c, int stage) {
        const int k0 = c << 5;
        const uint32_t sdst = sb + stage * STAGE_B;
        // 256 A chunks + 512 W chunks = 768 / 256 threads = 3 iters
        #pragma unroll
        for (int it = 0; it < 3; it++) {
            int gi = it * 256 + tid;
            uint32_t dst; const __half* src;
            if (gi < 256) {
                int row = gi >> 2, chunk = gi & 3;
                dst = sdst + row * 80 + chunk * 16;
                src = A + (size_t)(bm + row) * K + k0 + chunk * 8;
            } else {
                int li = gi - 256;
                int row = li >> 2, chunk = li & 3;
                int gn = bn + row; if (gn > N - 1) gn = N - 1;
                dst = sdst + A_TILE_B + row * 80 + chunk * 16;
                src = W + (size_t)gn * K + k0 + chunk * 8;
            }
            cp16(dst, src);
        }
    };

    #pragma unroll
    for (int s = 0; s < NSTAGE - 1; s++) {
        if (s < nc) load_stage(s, s);
        CP_COMMIT();
    }

    for (int c = 0; c < nc; c++) {
        cp_wait<NSTAGE - 2>();
        __syncthreads();

        if (c + NSTAGE - 1 < nc) load_stage(c + NSTAGE - 1, (c + NSTAGE - 1) % NSTAGE);
        CP_COMMIT();

        const uint32_t st = sb + (c % NSTAGE) * STAGE_B;
        #pragma unroll
        for (int ks = 0; ks < 2; ks++) {
            uint32_t fa[4][4], fb[2][2];
            {   // B frags: warp's own 16 columns (no cross-warp redundancy)
                int nrow = wn * 16 + (lane & 7) + 8 * (lane >> 4);
                uint32_t koff = ks * 32 + ((lane >> 3) & 1) * 16;
                uint32_t r0,r1,r2,r3;
                ldsm_x4(st + A_TILE_B + nrow * 80 + koff, r0, r1, r2, r3);
                fb[0][0]=r0; fb[0][1]=r1; fb[1][0]=r2; fb[1][1]=r3;
            }
            #pragma unroll
            for (int i = 0; i < 4; i++) {
                int mrow = i * 16 + (lane & 7) + 8 * ((lane >> 3) & 1);
                uint32_t koff = ks * 32 + (lane >> 4) * 16;
                ldsm_x4(st + mrow * 80 + koff, fa[i][0], fa[i][1], fa[i][2], fa[i][3]);
            }
            #pragma unroll
            for (int i = 0; i < 4; i++)
                #pragma unroll
                for (int j = 0; j < 2; j++)
                    mma16816f(acc[i][j], fa[i], fb[j]);
        }
    }

    // ---- epilogue: scalar stores (adjacent lanes contiguous; safe for odd N) ----
    #pragma unroll
    for (int i = 0; i < 4; i++) {
        int row0 = bm + i * 16 + (lane >> 2);
        #pragma unroll
        for (int j = 0; j < 2; j++) {
            int col = bn + wn * 16 + j * 8 + (lane & 3) * 2;
            float bv0 = 0.f, bv1 = 0.f;
            if (flags & FLAG_BIAS) {
                if (col < N)     bv0 = bias[col];
                if (col + 1 < N) bv1 = bias[col + 1];
            }
            #pragma unroll
            for (int half = 0; half < 2; half++) {
                int row = row0 + half * 8;
                float v0 = acc[i][j][2*half]     + bv0;
                float v1 = acc[i][j][2*half + 1] + bv1;
                if (flags & FLAG_GELU) {
                    v0 = 0.5f * v0 * (1.0f + erff(v0 * 0.7071067811865476f));
                    v1 = 0.5f * v1 * (1.0f + erff(v1 * 0.7071067811865476f));
                }
                size_t ci = (size_t)row * N + col;
                if (flags & FLAG_RES) {
                    if (col < N)     v0 += res[ci];
                    if (col + 1 < N) v1 += res[ci + 1];
                }
                if (flags & FLAG_F16OUT) {
                    if (col < N)     Cf[ci]   = __float2half(v0);
                    if (col + 1 < N) Cf[ci+1] = __float2half(v1);
                } else {
                    if (col < N)     C[ci]   = v0;
                    if (col + 1 < N) C[ci+1] = v1;
                }
            }
        }
    }
}

// ---------------- flash attention: 64 queries per block ----------------
#define ATT_SMEM (4 * 64 * 68 * 4)
__global__ __launch_bounds__(256)
void attn_flash(const float* __restrict__ qkv, __half* __restrict__ o) {
    extern __shared__ float sm[];
    float* Qs = sm;
    float* Ks = sm + 64 * 68;
    float* Vs = sm + 2 * 64 * 68;
    float* Ps = sm + 3 * 64 * 68;

    const int qt = blockIdx.x, h = blockIdx.y, b = blockIdx.z;
    const int tid = threadIdx.x;
    const int q   = tid >> 2;
    const int sg  = tid & 3;
    const int q_glob = qt * 64 + q;

    for (int i = tid; i < 64 * 16; i += 256) {
        int r = i >> 4, c4 = (i & 15);
        float4 v = *(const float4*)&qkv[((size_t)(b*Tt + qt*64 + r))*(3*Ee) + h*HDd + c4*4];
        *(float4*)&Qs[r * 68 + c4 * 4] = v;
    }

    float m_run = -1e30f, l_run = 0.f;
    float out[16];
    #pragma unroll
    for (int i = 0; i < 16; i++) out[i] = 0.f;
    __syncthreads();

    for (int kt = 0; kt <= qt; kt++) {
        for (int i = tid; i < 64 * 16; i += 256) {
            int r = i >> 4, c4 = (i & 15);
            size_t base = ((size_t)(b*Tt + kt*64 + r)) * (3*Ee) + h*HDd;
            float4 kv = *(const float4*)&qkv[base + Ee   + c4*4];
            float4 vv = *(const float4*)&qkv[base + 2*Ee + c4*4];
            *(float4*)&Ks[r * 68 + (c4 ^ ((r >> 4) & 3)) * 4] = kv;
            *(float4*)&Vs[r * 68 + c4 * 4] = vv;
        }
        __syncthreads();

        float s[16];
        #pragma unroll
        for (int kk = 0; kk < 16; kk++) s[kk] = 0.f;
        #pragma unroll
        for (int d4 = 0; d4 < 16; d4++) {
            float4 qv = *(const float4*)&Qs[q * 68 + d4 * 4];
            #pragma unroll
            for (int kk = 0; kk < 16; kk++) {
                int krow = sg * 16 + kk;
                float4 kv = *(const float4*)&Ks[krow * 68 + (d4 ^ sg) * 4];
                s[kk] = fmaf(qv.x, kv.x, fmaf(qv.y, kv.y, fmaf(qv.z, kv.z, fmaf(qv.w, kv.w, s[kk]))));
            }
        }
        const int k0g = kt * 64 + sg * 16;
        float lmax = -1e30f;
        #pragma unroll
        for (int kk = 0; kk < 16; kk++) {
            s[kk] *= 0.125f;
            if (k0g + kk > q_glob) s[kk] = -1e30f;
            lmax = fmaxf(lmax, s[kk]);
        }
        lmax = fmaxf(lmax, __shfl_xor_sync(0xFFFFFFFFu, lmax, 1));
        lmax = fmaxf(lmax, __shfl_xor_sync(0xFFFFFFFFu, lmax, 2));
        float mnew = fmaxf(m_run, lmax);
        float f = __expf(m_run - mnew);
        l_run *= f;
        #pragma unroll
        for (int i = 0; i < 16; i++) out[i] *= f;
        float psum = 0.f;
        #pragma unroll
        for (int kk = 0; kk < 16; kk++) {
            float p = __expf(s[kk] - mnew);
            psum += p;
            Ps[q * 68 + sg * 16 + kk] = p;
        }
        psum += __shfl_xor_sync(0xFFFFFFFFu, psum, 1);
        psum += __shfl_xor_sync(0xFFFFFFFFu, psum, 2);
        l_run += psum;
        m_run = mnew;
        __syncwarp();

        for (int k = 0; k < 64; k++) {
            float p = Ps[q * 68 + k];
            #pragma unroll
            for (int d4i = 0; d4i < 4; d4i++) {
                float4 vv = *(const float4*)&Vs[k * 68 + sg * 16 + d4i * 4];
                out[d4i*4+0] = fmaf(p, vv.x, out[d4i*4+0]);
                out[d4i*4+1] = fmaf(p, vv.y, out[d4i*4+1]);
                out[d4i*4+2] = fmaf(p, vv.z, out[d4i*4+2]);
                out[d4i*4+3] = fmaf(p, vv.w, out[d4i*4+3]);
            }
        }
        __syncthreads();
    }

    float inv = 1.0f / l_run;
    size_t obase = ((size_t)(b*Tt + q_glob)) * Ee + h * HDd + sg * 16;
    #pragma unroll
    for (int i = 0; i < 16; i++)
        o[obase + i] = __float2half(out[i] * inv);
}

// ---------------- launcher ----------------
static void run_gemm(const __half* A, const __half* W,
                     const float* bias, const float* res,
                     float* C, __half* Cf, int N, int K, int flags) {
    dim3 g(BT / 64, (N + 127) / 128);
    gemm_mma<<<g, 256, GEMM_SMEM>>>(A, W, bias, res, C, Cf, N, K, flags);
}

extern "C" void kernel_launch(void* const* d_in, const int* in_sizes, int n_in,
                              void* d_out, int out_size) {
    const int*   input_ids = (const int*)  d_in[0];
    const float* tok_emb   = (const float*)d_in[1];
    const float* pos_emb   = (const float*)d_in[2];
    const float* ln1_scale = (const float*)d_in[3];
    const float* ln1_bias  = (const float*)d_in[4];
    const float* qkv_w     = (const float*)d_in[5];
    const float* out_w     = (const float*)d_in[6];
    const float* ln2_scale = (const float*)d_in[7];
    const float* ln2_bias  = (const float*)d_in[8];
    const float* fc1_w     = (const float*)d_in[9];
    const float* fc1_b     = (const float*)d_in[10];
    const float* fc2_w     = (const float*)d_in[11];
    const float* fc2_b     = (const float*)d_in[12];
    const float* lnf_scale = (const float*)d_in[13];
    const float* lnf_bias  = (const float*)d_in[14];
    float* logits = (float*)d_out;

    cudaFuncSetAttribute((const void*)gemm_mma,   cudaFuncAttributeMaxDynamicSharedMemorySize, GEMM_SMEM);
    cudaFuncSetAttribute((const void*)attn_flash, cudaFuncAttributeMaxDynamicSharedMemorySize, ATT_SMEM);

    float *x, *qkv;
    __half *h, *at, *f, *qw, *ow, *f1, *f2, *te;
    cudaGetSymbolAddress((void**)&x,   g_x);
    cudaGetSymbolAddress((void**)&qkv, g_qkv);
    cudaGetSymbolAddress((void**)&h,   g_h);
    cudaGetSymbolAddress((void**)&at,  g_at);
    cudaGetSymbolAddress((void**)&f,   g_f);
    cudaGetSymbolAddress((void**)&qw,  g_qw);  cudaGetSymbolAddress((void**)&ow,  g_ow);
    cudaGetSymbolAddress((void**)&f1,  g_f1);  cudaGetSymbolAddress((void**)&f2,  g_f2);
    cudaGetSymbolAddress((void**)&te,  g_te);

    // single merged weight conversion
    conv_all_kernel<<<(C_TOT + 255) / 256, 256>>>(qkv_w, out_w, fc1_w, fc2_w, tok_emb,
                                                  qw, ow, f1, f2, te);

    embed_kernel<<<(BT * Ee + 255) / 256, 256>>>(input_ids, tok_emb, pos_emb, x);

    for (int l = 0; l < Ll; l++) {
        // attention block (pre-norm)
        ln_kernel<<<BT, 256>>>(x, ln1_scale + l * Ee, ln1_bias + l * Ee, h);
        run_gemm(h, qw + (size_t)l * 3 * Ee * Ee,
                 nullptr, nullptr, qkv, nullptr, 3 * Ee, Ee, 0);
        attn_flash<<<dim3(Tt/64, NHh, Bb), 256, ATT_SMEM>>>(qkv, at);
        run_gemm(at, ow + (size_t)l * Ee * Ee,
                 nullptr, x, x, nullptr, Ee, Ee, FLAG_RES);
        // FFN block (pre-norm)
        ln_kernel<<<BT, 256>>>(x, ln2_scale + l * Ee, ln2_bias + l * Ee, h);
        run_gemm(h, f1 + (size_t)l * FFf * Ee,
                 fc1_b + (size_t)l * FFf, nullptr, nullptr, f,
                 FFf, Ee, FLAG_BIAS | FLAG_GELU | FLAG_F16OUT);
        run_gemm(f, f2 + (size_t)l * Ee * FFf,
                 fc2_b + (size_t)l * Ee, x, x, nullptr,
                 Ee, FFf, FLAG_BIAS | FLAG_RES);
    }

    // final layernorm + tied LM head
    ln_kernel<<<BT, 256>>>(x, lnf_scale, lnf_bias, h);
    run_gemm(h, te, nullptr, nullptr, logits, nullptr, Vv, Ee, 0);
}

// round 14
// speedup vs baseline: 1.1092x; 1.1092x over previous
#include <cuda_runtime.h>
#include <cuda_bf16.h>
#include <cuda_fp16.h>
#include <cstdint>
#include <math.h>

// ---------------- problem constants ----------------
#define Vv 50257
#define Ee 768
#define NHh 12
#define HDd 64
#define Ll 4
#define Tt 1024
#define Bb 2
#define FFf 3072
#define BT (Bb*Tt)            // 2048 rows

// ---------------- scratch (static, no allocs) ----------------
__device__ float g_x  [BT * Ee];                 // residual stream (fp32)
__device__ float g_qkv[BT * 3*Ee];               // qkv projection (fp32)
__device__ __half g_h [BT*Ee];                   // LN output fp16
__device__ __half g_at[BT*Ee];                   // attn output fp16
__device__ __half g_f [BT*FFf];                  // ffn hidden fp16
// weights, single fp16
__device__ __half g_qw[Ll*3*Ee*Ee];
__device__ __half g_ow[Ll*Ee*Ee];
__device__ __half g_f1[Ll*FFf*Ee];
__device__ __half g_f2[Ll*Ee*FFf];
__device__ __half g_te[Vv*Ee];

__device__ __forceinline__ uint32_t smem_u32(const void* p) {
    uint32_t a;
    asm("{ .reg .u64 t; cvta.to.shared.u64 t, %1; cvt.u32.u64 %0, t; }" : "=r"(a) : "l"(p));
    return a;
}
__device__ __forceinline__ void cp16(uint32_t dst, const void* src) {
    asm volatile("cp.async.cg.shared.global [%0], [%1], 16;" :: "r"(dst), "l"(src));
}
#define CP_COMMIT() asm volatile("cp.async.commit_group;" ::: "memory")
template<int N> __device__ __forceinline__ void cp_wait() {
    asm volatile("cp.async.wait_group %0;" :: "n"(N) : "memory");
}

__device__ __forceinline__ void ldsm_x4(uint32_t a, uint32_t& r0, uint32_t& r1, uint32_t& r2, uint32_t& r3) {
    asm volatile("ldmatrix.sync.aligned.m8n8.x4.shared.b16 {%0,%1,%2,%3}, [%4];"
                 : "=r"(r0), "=r"(r1), "=r"(r2), "=r"(r3) : "r"(a));
}
__device__ __forceinline__ void mma16816f(float* d, const uint32_t* a, const uint32_t* b) {
    asm volatile("mma.sync.aligned.m16n8k16.row.col.f32.f16.f16.f32 "
                 "{%0,%1,%2,%3}, {%4,%5,%6,%7}, {%8,%9}, {%0,%1,%2,%3};"
                 : "+f"(d[0]), "+f"(d[1]), "+f"(d[2]), "+f"(d[3])
                 : "r"(a[0]), "r"(a[1]), "r"(a[2]), "r"(a[3]), "r"(b[0]), "r"(b[1]));
}

// ---------------- merged fp32 -> fp16 weight conversion (one launch) ----------------
#define C_QW (Ll*3*Ee*Ee/4)
#define C_OW (Ll*Ee*Ee/4)
#define C_F1 (Ll*FFf*Ee/4)
#define C_F2 (Ll*Ee*FFf/4)
#define C_TE (Vv*Ee/4)
#define C_TOT (C_QW + C_OW + C_F1 + C_F2 + C_TE)

__global__ void conv_all_kernel(const float* __restrict__ qkv_w, const float* __restrict__ out_w,
                                const float* __restrict__ fc1_w, const float* __restrict__ fc2_w,
                                const float* __restrict__ tok_emb,
                                __half* __restrict__ qw, __half* __restrict__ ow,
                                __half* __restrict__ f1, __half* __restrict__ f2,
                                __half* __restrict__ te) {
    int i = blockIdx.x * blockDim.x + threadIdx.x;
    if (i >= C_TOT) return;
    const float* src; __half* dst; int off = i;
    if (off < C_QW)                        { src = qkv_w;  dst = qw; }
    else if ((off -= C_QW) < C_OW)         { src = out_w;  dst = ow; }
    else if ((off -= C_OW) < C_F1)         { src = fc1_w;  dst = f1; }
    else if ((off -= C_F1) < C_F2)         { src = fc2_w;  dst = f2; }
    else      { off -= C_F2;                 src = tok_emb; dst = te; }
    float4 v = ((const float4*)src)[off];
    __half2 a, b;
    a.x = __float2half(v.x); a.y = __float2half(v.y);
    b.x = __float2half(v.z); b.y = __float2half(v.w);
    ((__half2*)dst)[2*off]   = a;
    ((__half2*)dst)[2*off+1] = b;
}

// ---------------- embedding ----------------
__global__ void embed_kernel(const int* __restrict__ ids, const float* __restrict__ tok,
                             const float* __restrict__ pos, float* __restrict__ out) {
    int i = blockIdx.x * blockDim.x + threadIdx.x;
    if (i >= BT * Ee) return;
    int e = i % Ee, row = i / Ee, t = row % Tt;
    out[i] = tok[(size_t)ids[row] * Ee + e] + pos[t * Ee + e];
}

// ---------------- layernorm -> fp16 ----------------
__global__ void ln_kernel(const float* __restrict__ x,
                          const float* __restrict__ scale, const float* __restrict__ bias,
                          __half* __restrict__ o) {
    __shared__ float s1[256], s2[256];
    int row = blockIdx.x, tid = threadIdx.x;
    const float* xr = x + (size_t)row * Ee;
    float sum = 0.f, sq = 0.f;
    for (int c = tid; c < Ee; c += 256) { float v = xr[c]; sum += v; sq += v * v; }
    s1[tid] = sum; s2[tid] = sq; __syncthreads();
    for (int s = 128; s > 0; s >>= 1) {
        if (tid < s) { s1[tid] += s1[tid+s]; s2[tid] += s2[tid+s]; }
        __syncthreads();
    }
    float mean = s1[0] * (1.0f / Ee);
    float var  = s2[0] * (1.0f / Ee) - mean * mean;
    float rstd = rsqrtf(var + 1e-5f);
    for (int c = tid; c < Ee; c += 256) {
        float v = (xr[c] - mean) * rstd * scale[c] + bias[c];
        o[(size_t)row * Ee + c] = __float2half(v);
    }
}

// ---------------- HMMA GEMM flags ----------------
#define FLAG_BIAS 1
#define FLAG_GELU 2
#define FLAG_RES  4
#define FLAG_F16OUT 8

__device__ __forceinline__ void epi_store(float v0, float v1, int row, int col, int N,
                                          const float* bias, const float* res,
                                          float* C, __half* Cf, int flags) {
    if (flags & FLAG_BIAS) {
        if (col < N)     v0 += bias[col];
        if (col + 1 < N) v1 += bias[col + 1];
    }
    if (flags & FLAG_GELU) {
        v0 = 0.5f * v0 * (1.0f + erff(v0 * 0.7071067811865476f));
        v1 = 0.5f * v1 * (1.0f + erff(v1 * 0.7071067811865476f));
    }
    size_t ci = (size_t)row * N + col;
    if (flags & FLAG_RES) {
        if (col < N)     v0 += res[ci];
        if (col + 1 < N) v1 += res[ci + 1];
    }
    if (flags & FLAG_F16OUT) {
        if (col < N)     Cf[ci]   = __float2half(v0);
        if (col + 1 < N) Cf[ci+1] = __float2half(v1);
    } else {
        if (col < N)     C[ci]   = v0;
        if (col + 1 < N) C[ci+1] = v1;
    }
}

#define NSTAGE 3

// ======== WIDE: BM=128, BN=128, 2 CTAs/SM (R12 config — best measured) ========
#define A_TILE_W (128 * 80)     // 10240
#define W_TILE_W (128 * 80)     // 10240
#define STAGE_W  (A_TILE_W + W_TILE_W)
#define GEMM_SMEM_W (NSTAGE * STAGE_W)   // 61440

__global__ __launch_bounds__(256, 2)
void gemm_wide(const __half* __restrict__ A, const __half* __restrict__ W,
               const float* __restrict__ bias, const float* __restrict__ res,
               float* __restrict__ C, __half* __restrict__ Cf,
               int N, int K, int flags) {
    extern __shared__ char smem[];
    const uint32_t sb = smem_u32(smem);
    const int tid  = threadIdx.x;
    const int lane = tid & 31;
    const int wid  = tid >> 5;
    const int wm   = wid >> 2;           // 0..1 : 64-row band
    const int wn   = wid & 3;            // 0..3 : 32-col band
    const int bm   = blockIdx.x * 128;
    const int bn   = blockIdx.y * 128;

    float acc[4][4][4];
    #pragma unroll
    for (int i = 0; i < 4; i++)
        #pragma unroll
        for (int j = 0; j < 4; j++)
            #pragma unroll
            for (int r = 0; r < 4; r++) acc[i][j][r] = 0.f;

    const int nc = K >> 5;

    auto load_stage = [&](int c, int stage) {
        const int k0 = c << 5;
        const uint32_t sdst = sb + stage * STAGE_W;
        #pragma unroll
        for (int it = 0; it < 4; it++) {      // 512 A + 512 W chunks
            int gi = it * 256 + tid;
            uint32_t dst; const __half* src;
            if (gi < 512) {
                int row = gi >> 2, chunk = gi & 3;
                dst = sdst + row * 80 + chunk * 16;
                src = A + (size_t)(bm + row) * K + k0 + chunk * 8;
            } else {
                int li = gi - 512;
                int row = li >> 2, chunk = li & 3;
                int gn = bn + row; if (gn > N - 1) gn = N - 1;
                dst = sdst + A_TILE_W + row * 80 + chunk * 16;
                src = W + (size_t)gn * K + k0 + chunk * 8;
            }
            cp16(dst, src);
        }
    };

    #pragma unroll
    for (int s = 0; s < NSTAGE - 1; s++) {
        if (s < nc) load_stage(s, s);
        CP_COMMIT();
    }

    for (int c = 0; c < nc; c++) {
        cp_wait<NSTAGE - 2>();
        __syncthreads();

        if (c + NSTAGE - 1 < nc) load_stage(c + NSTAGE - 1, (c + NSTAGE - 1) % NSTAGE);
        CP_COMMIT();

        const uint32_t st = sb + (c % NSTAGE) * STAGE_W;
        #pragma unroll
        for (int ks = 0; ks < 2; ks++) {
            uint32_t fa[4][4], fb[4][2];
            #pragma unroll
            for (int p = 0; p < 2; p++) {
                int nrow = wn * 32 + p * 16 + (lane & 7) + 8 * (lane >> 4);
                uint32_t koff = ks * 32 + ((lane >> 3) & 1) * 16;
                uint32_t r0,r1,r2,r3;
                ldsm_x4(st + A_TILE_W + nrow * 80 + koff, r0, r1, r2, r3);
                fb[2*p][0]=r0; fb[2*p][1]=r1; fb[2*p+1][0]=r2; fb[2*p+1][1]=r3;
            }
            #pragma unroll
            for (int i = 0; i < 4; i++) {
                int mrow = wm * 64 + i * 16 + (lane & 7) + 8 * ((lane >> 3) & 1);
                uint32_t koff = ks * 32 + (lane >> 4) * 16;
                ldsm_x4(st + mrow * 80 + koff, fa[i][0], fa[i][1], fa[i][2], fa[i][3]);
            }
            #pragma unroll
            for (int i = 0; i < 4; i++)
                #pragma unroll
                for (int j = 0; j < 4; j++)
                    mma16816f(acc[i][j], fa[i], fb[j]);
        }
    }

    #pragma unroll
    for (int i = 0; i < 4; i++) {
        int row0 = bm + wm * 64 + i * 16 + (lane >> 2);
        #pragma unroll
        for (int j = 0; j < 4; j++) {
            int col = bn + wn * 32 + j * 8 + (lane & 3) * 2;
            #pragma unroll
            for (int half = 0; half < 2; half++)
                epi_store(acc[i][j][2*half], acc[i][j][2*half+1],
                          row0 + half * 8, col, N, bias, res, C, Cf, flags);
        }
    }
}

// ======== NARROW: BM=64, BN=64, 3 CTAs/SM (for N=768 GEMMs; grid 32x12) ========
#define A_TILE_N (64 * 80)      // 5120
#define W_TILE_N (64 * 80)      // 5120
#define STAGE_N  (A_TILE_N + W_TILE_N)
#define GEMM_SMEM_N (NSTAGE * STAGE_N)   // 30720

__global__ __launch_bounds__(256, 3)
void gemm_n64(const __half* __restrict__ A, const __half* __restrict__ W,
              const float* __restrict__ bias, const float* __restrict__ res,
              float* __restrict__ C, __half* __restrict__ Cf,
              int N, int K, int flags) {
    extern __shared__ char smem[];
    const uint32_t sb = smem_u32(smem);
    const int tid  = threadIdx.x;
    const int lane = tid & 31;
    const int wid  = tid >> 5;
    const int wm   = wid >> 2;           // 0..1 : 32-row band
    const int wn   = wid & 3;            // 0..3 : 16-col band
    const int bm   = blockIdx.x * 64;
    const int bn   = blockIdx.y * 64;

    float acc[2][2][4];
    #pragma unroll
    for (int i = 0; i < 2; i++)
        #pragma unroll
        for (int j = 0; j < 2; j++)
            #pragma unroll
            for (int r = 0; r < 4; r++) acc[i][j][r] = 0.f;

    const int nc = K >> 5;

    auto load_stage = [&](int c, int stage) {
        const int k0 = c << 5;
        const uint32_t sdst = sb + stage * STAGE_N;
        #pragma unroll
        for (int it = 0; it < 2; it++) {      // 256 A + 256 W chunks
            int gi = it * 256 + tid;
            uint32_t dst; const __half* src;
            if (gi < 256) {
                int row = gi >> 2, chunk = gi & 3;
                dst = sdst + row * 80 + chunk * 16;
                src = A + (size_t)(bm + row) * K + k0 + chunk * 8;
            } else {
                int li = gi - 256;
                int row = li >> 2, chunk = li & 3;
                int gn = bn + row; if (gn > N - 1) gn = N - 1;
                dst = sdst + A_TILE_N + row * 80 + chunk * 16;
                src = W + (size_t)gn * K + k0 + chunk * 8;
            }
            cp16(dst, src);
        }
    };

    #pragma unroll
    for (int s = 0; s < NSTAGE - 1; s++) {
        if (s < nc) load_stage(s, s);
        CP_COMMIT();
    }

    for (int c = 0; c < nc; c++) {
        cp_wait<NSTAGE - 2>();
        __syncthreads();

        if (c + NSTAGE - 1 < nc) load_stage(c + NSTAGE - 1, (c + NSTAGE - 1) % NSTAGE);
        CP_COMMIT();

        const uint32_t st = sb + (c % NSTAGE) * STAGE_N;
        #pragma unroll
        for (int ks = 0; ks < 2; ks++) {
            uint32_t fa[2][4], fb[2][2];
            {
                int nrow = wn * 16 + (lane & 7) + 8 * (lane >> 4);
                uint32_t koff = ks * 32 + ((lane >> 3) & 1) * 16;
                uint32_t r0,r1,r2,r3;
                ldsm_x4(st + A_TILE_N + nrow * 80 + koff, r0, r1, r2, r3);
                fb[0][0]=r0; fb[0][1]=r1; fb[1][0]=r2; fb[1][1]=r3;
            }
            #pragma unroll
            for (int i = 0; i < 2; i++) {
                int mrow = wm * 32 + i * 16 + (lane & 7) + 8 * ((lane >> 3) & 1);
                uint32_t koff = ks * 32 + (lane >> 4) * 16;
                ldsm_x4(st + mrow * 80 + koff, fa[i][0], fa[i][1], fa[i][2], fa[i][3]);
            }
            #pragma unroll
            for (int i = 0; i < 2; i++)
                #pragma unroll
                for (int j = 0; j < 2; j++)
                    mma16816f(acc[i][j], fa[i], fb[j]);
        }
    }

    #pragma unroll
    for (int i = 0; i < 2; i++) {
        int row0 = bm + wm * 32 + i * 16 + (lane >> 2);
        #pragma unroll
        for (int j = 0; j < 2; j++) {
            int col = bn + wn * 16 + j * 8 + (lane & 3) * 2;
            #pragma unroll
            for (int half = 0; half < 2; half++)
                epi_store(acc[i][j][2*half], acc[i][j][2*half+1],
                          row0 + half * 8, col, N, bias, res, C, Cf, flags);
        }
    }
}

// ---------------- flash attention: 64 queries per block ----------------
#define ATT_SMEM (4 * 64 * 68 * 4)
__global__ __launch_bounds__(256)
void attn_flash(const float* __restrict__ qkv, __half* __restrict__ o) {
    extern __shared__ float sm[];
    float* Qs = sm;
    float* Ks = sm + 64 * 68;
    float* Vs = sm + 2 * 64 * 68;
    float* Ps = sm + 3 * 64 * 68;

    const int qt = blockIdx.x, h = blockIdx.y, b = blockIdx.z;
    const int tid = threadIdx.x;
    const int q   = tid >> 2;
    const int sg  = tid & 3;
    const int q_glob = qt * 64 + q;

    for (int i = tid; i < 64 * 16; i += 256) {
        int r = i >> 4, c4 = (i & 15);
        float4 v = *(const float4*)&qkv[((size_t)(b*Tt + qt*64 + r))*(3*Ee) + h*HDd + c4*4];
        *(float4*)&Qs[r * 68 + c4 * 4] = v;
    }

    float m_run = -1e30f, l_run = 0.f;
    float out[16];
    #pragma unroll
    for (int i = 0; i < 16; i++) out[i] = 0.f;
    __syncthreads();

    for (int kt = 0; kt <= qt; kt++) {
        for (int i = tid; i < 64 * 16; i += 256) {
            int r = i >> 4, c4 = (i & 15);
            size_t base = ((size_t)(b*Tt + kt*64 + r)) * (3*Ee) + h*HDd;
            float4 kv = *(const float4*)&qkv[base + Ee   + c4*4];
            float4 vv = *(const float4*)&qkv[base + 2*Ee + c4*4];
            *(float4*)&Ks[r * 68 + (c4 ^ ((r >> 4) & 3)) * 4] = kv;
            *(float4*)&Vs[r * 68 + c4 * 4] = vv;
        }
        __syncthreads();

        float s[16];
        #pragma unroll
        for (int kk = 0; kk < 16; kk++) s[kk] = 0.f;
        #pragma unroll
        for (int d4 = 0; d4 < 16; d4++) {
            float4 qv = *(const float4*)&Qs[q * 68 + d4 * 4];
            #pragma unroll
            for (int kk = 0; kk < 16; kk++) {
                int krow = sg * 16 + kk;
                float4 kv = *(const float4*)&Ks[krow * 68 + (d4 ^ sg) * 4];
                s[kk] = fmaf(qv.x, kv.x, fmaf(qv.y, kv.y, fmaf(qv.z, kv.z, fmaf(qv.w, kv.w, s[kk]))));
            }
        }
        const int k0g = kt * 64 + sg * 16;
        float lmax = -1e30f;
        #pragma unroll
        for (int kk = 0; kk < 16; kk++) {
            s[kk] *= 0.125f;
            if (k0g + kk > q_glob) s[kk] = -1e30f;
            lmax = fmaxf(lmax, s[kk]);
        }
        lmax = fmaxf(lmax, __shfl_xor_sync(0xFFFFFFFFu, lmax, 1));
        lmax = fmaxf(lmax, __shfl_xor_sync(0xFFFFFFFFu, lmax, 2));
        float mnew = fmaxf(m_run, lmax);
        float f = __expf(m_run - mnew);
        l_run *= f;
        #pragma unroll
        for (int i = 0; i < 16; i++) out[i] *= f;
        float psum = 0.f;
        #pragma unroll
        for (int kk = 0; kk < 16; kk++) {
            float p = __expf(s[kk] - mnew);
            psum += p;
            Ps[q * 68 + sg * 16 + kk] = p;
        }
        psum += __shfl_xor_sync(0xFFFFFFFFu, psum, 1);
        psum += __shfl_xor_sync(0xFFFFFFFFu, psum, 2);
        l_run += psum;
        m_run = mnew;
        __syncwarp();

        for (int k = 0; k < 64; k++) {
            float p = Ps[q * 68 + k];
            #pragma unroll
            for (int d4i = 0; d4i < 4; d4i++) {
                float4 vv = *(const float4*)&Vs[k * 68 + sg * 16 + d4i * 4];
                out[d4i*4+0] = fmaf(p, vv.x, out[d4i*4+0]);
                out[d4i*4+1] = fmaf(p, vv.y, out[d4i*4+1]);
                out[d4i*4+2] = fmaf(p, vv.z, out[d4i*4+2]);
                out[d4i*4+3] = fmaf(p, vv.w, out[d4i*4+3]);
            }
        }
        __syncthreads();
    }

    float inv = 1.0f / l_run;
    size_t obase = ((size_t)(b*Tt + q_glob)) * Ee + h * HDd + sg * 16;
    #pragma unroll
    for (int i = 0; i < 16; i++)
        o[obase + i] = __float2half(out[i] * inv);
}

// ---------------- launcher ----------------
static void run_wide(const __half* A, const __half* W,
                     const float* bias, const float* res,
                     float* C, __half* Cf, int N, int K, int flags) {
    dim3 g(BT / 128, (N + 127) / 128);
    gemm_wide<<<g, 256, GEMM_SMEM_W>>>(A, W, bias, res, C, Cf, N, K, flags);
}
static void run_narrow(const __half* A, const __half* W,
                       const float* bias, const float* res,
                       float* C, __half* Cf, int N, int K, int flags) {
    dim3 g(BT / 64, (N + 63) / 64);
    gemm_n64<<<g, 256, GEMM_SMEM_N>>>(A, W, bias, res, C, Cf, N, K, flags);
}

extern "C" void kernel_launch(void* const* d_in, const int* in_sizes, int n_in,
                              void* d_out, int out_size) {
    const int*   input_ids = (const int*)  d_in[0];
    const float* tok_emb   = (const float*)d_in[1];
    const float* pos_emb   = (const float*)d_in[2];
    const float* ln1_scale = (const float*)d_in[3];
    const float* ln1_bias  = (const float*)d_in[4];
    const float* qkv_w     = (const float*)d_in[5];
    const float* out_w     = (const float*)d_in[6];
    const float* ln2_scale = (const float*)d_in[7];
    const float* ln2_bias  = (const float*)d_in[8];
    const float* fc1_w     = (const float*)d_in[9];
    const float* fc1_b     = (const float*)d_in[10];
    const float* fc2_w     = (const float*)d_in[11];
    const float* fc2_b     = (const float*)d_in[12];
    const float* lnf_scale = (const float*)d_in[13];
    const float* lnf_bias  = (const float*)d_in[14];
    float* logits = (float*)d_out;

    cudaFuncSetAttribute((const void*)gemm_wide,  cudaFuncAttributeMaxDynamicSharedMemorySize, GEMM_SMEM_W);
    cudaFuncSetAttribute((const void*)gemm_n64,   cudaFuncAttributeMaxDynamicSharedMemorySize, GEMM_SMEM_N);
    cudaFuncSetAttribute((const void*)attn_flash, cudaFuncAttributeMaxDynamicSharedMemorySize, ATT_SMEM);

    float *x, *qkv;
    __half *h, *at, *f, *qw, *ow, *f1, *f2, *te;
    cudaGetSymbolAddress((void**)&x,   g_x);
    cudaGetSymbolAddress((void**)&qkv, g_qkv);
    cudaGetSymbolAddress((void**)&h,   g_h);
    cudaGetSymbolAddress((void**)&at,  g_at);
    cudaGetSymbolAddress((void**)&f,   g_f);
    cudaGetSymbolAddress((void**)&qw,  g_qw);  cudaGetSymbolAddress((void**)&ow,  g_ow);
    cudaGetSymbolAddress((void**)&f1,  g_f1);  cudaGetSymbolAddress((void**)&f2,  g_f2);
    cudaGetSymbolAddress((void**)&te,  g_te);

    // single merged weight conversion
    conv_all_kernel<<<(C_TOT + 255) / 256, 256>>>(qkv_w, out_w, fc1_w, fc2_w, tok_emb,
                                                  qw, ow, f1, f2, te);

    embed_kernel<<<(BT * Ee + 255) / 256, 256>>>(input_ids, tok_emb, pos_emb, x);

    for (int l = 0; l < Ll; l++) {
        // attention block (pre-norm)
        ln_kernel<<<BT, 256>>>(x, ln1_scale + l * Ee, ln1_bias + l * Ee, h);
        run_wide(h, qw + (size_t)l * 3 * Ee * Ee,
                 nullptr, nullptr, qkv, nullptr, 3 * Ee, Ee, 0);
        attn_flash<<<dim3(Tt/64, NHh, Bb), 256, ATT_SMEM>>>(qkv, at);
        run_narrow(at, ow + (size_t)l * Ee * Ee,
                   nullptr, x, x, nullptr, Ee, Ee, FLAG_RES);
        // FFN block (pre-norm)
        ln_kernel<<<BT, 256>>>(x, ln2_scale + l * Ee, ln2_bias + l * Ee, h);
        run_wide(h, f1 + (size_t)l * FFf * Ee,
                 fc1_b + (size_t)l * FFf, nullptr, nullptr, f,
                 FFf, Ee, FLAG_BIAS | FLAG_GELU | FLAG_F16OUT);
        run_narrow(f, f2 + (size_t)l * Ee * FFf,
                   fc2_b + (size_t)l * Ee, x, x, nullptr,
                   Ee, FFf, FLAG_BIAS | FLAG_RES);
    }

    // final layernorm + tied LM head
    ln_kernel<<<BT, 256>>>(x, lnf_scale, lnf_bias, h);
    run_wide(h, te, nullptr, nullptr, logits, nullptr, Vv, Ee, 0);
}

// round 15
// speedup vs baseline: 1.1919x; 1.0745x over previous
#include <cuda_runtime.h>
#include <cuda_bf16.h>
#include <cuda_fp16.h>
#include <cstdint>
#include <math.h>

// ---------------- problem constants ----------------
#define Vv 50257
#define Ee 768
#define NHh 12
#define HDd 64
#define Ll 4
#define Tt 1024
#define Bb 2
#define FFf 3072
#define BT (Bb*Tt)            // 2048 rows

// ---------------- scratch (static, no allocs) ----------------
__device__ float g_x  [BT * Ee];                 // residual stream (fp32)
__device__ float g_qkv[BT * 3*Ee];               // qkv projection (fp32)
__device__ __half g_h [BT*Ee];                   // LN output fp16
__device__ __half g_at[BT*Ee];                   // attn output fp16
__device__ __half g_f [BT*FFf];                  // ffn hidden fp16
// weights, single fp16
__device__ __half g_qw[Ll*3*Ee*Ee];
__device__ __half g_ow[Ll*Ee*Ee];
__device__ __half g_f1[Ll*FFf*Ee];
__device__ __half g_f2[Ll*Ee*FFf];
__device__ __half g_te[Vv*Ee];

__device__ __forceinline__ uint32_t smem_u32(const void* p) {
    uint32_t a;
    asm("{ .reg .u64 t; cvta.to.shared.u64 t, %1; cvt.u32.u64 %0, t; }" : "=r"(a) : "l"(p));
    return a;
}
__device__ __forceinline__ void cp16(uint32_t dst, const void* src) {
    asm volatile("cp.async.cg.shared.global [%0], [%1], 16;" :: "r"(dst), "l"(src));
}
#define CP_COMMIT() asm volatile("cp.async.commit_group;" ::: "memory")
template<int N> __device__ __forceinline__ void cp_wait() {
    asm volatile("cp.async.wait_group %0;" :: "n"(N) : "memory");
}

__device__ __forceinline__ void ldsm_x4(uint32_t a, uint32_t& r0, uint32_t& r1, uint32_t& r2, uint32_t& r3) {
    asm volatile("ldmatrix.sync.aligned.m8n8.x4.shared.b16 {%0,%1,%2,%3}, [%4];"
                 : "=r"(r0), "=r"(r1), "=r"(r2), "=r"(r3) : "r"(a));
}
__device__ __forceinline__ void mma16816f(float* d, const uint32_t* a, const uint32_t* b) {
    asm volatile("mma.sync.aligned.m16n8k16.row.col.f32.f16.f16.f32 "
                 "{%0,%1,%2,%3}, {%4,%5,%6,%7}, {%8,%9}, {%0,%1,%2,%3};"
                 : "+f"(d[0]), "+f"(d[1]), "+f"(d[2]), "+f"(d[3])
                 : "r"(a[0]), "r"(a[1]), "r"(a[2]), "r"(a[3]), "r"(b[0]), "r"(b[1]));
}

// ---------------- merged fp32 -> fp16 weight conversion (one launch) ----------------
#define C_QW (Ll*3*Ee*Ee/4)
#define C_OW (Ll*Ee*Ee/4)
#define C_F1 (Ll*FFf*Ee/4)
#define C_F2 (Ll*Ee*FFf/4)
#define C_TE (Vv*Ee/4)
#define C_TOT (C_QW + C_OW + C_F1 + C_F2 + C_TE)

__global__ void conv_all_kernel(const float* __restrict__ qkv_w, const float* __restrict__ out_w,
                                const float* __restrict__ fc1_w, const float* __restrict__ fc2_w,
                                const float* __restrict__ tok_emb,
                                __half* __restrict__ qw, __half* __restrict__ ow,
                                __half* __restrict__ f1, __half* __restrict__ f2,
                                __half* __restrict__ te) {
    int i = blockIdx.x * blockDim.x + threadIdx.x;
    if (i >= C_TOT) return;
    const float* src; __half* dst; int off = i;
    if (off < C_QW)                        { src = qkv_w;  dst = qw; }
    else if ((off -= C_QW) < C_OW)         { src = out_w;  dst = ow; }
    else if ((off -= C_OW) < C_F1)         { src = fc1_w;  dst = f1; }
    else if ((off -= C_F1) < C_F2)         { src = fc2_w;  dst = f2; }
    else      { off -= C_F2;                 src = tok_emb; dst = te; }
    float4 v = ((const float4*)src)[off];
    __half2 a, b;
    a.x = __float2half(v.x); a.y = __float2half(v.y);
    b.x = __float2half(v.z); b.y = __float2half(v.w);
    ((__half2*)dst)[2*off]   = a;
    ((__half2*)dst)[2*off+1] = b;
}

// ---------------- embedding ----------------
__global__ void embed_kernel(const int* __restrict__ ids, const float* __restrict__ tok,
                             const float* __restrict__ pos, float* __restrict__ out) {
    int i = blockIdx.x * blockDim.x + threadIdx.x;
    if (i >= BT * Ee) return;
    int e = i % Ee, row = i / Ee, t = row % Tt;
    out[i] = tok[(size_t)ids[row] * Ee + e] + pos[t * Ee + e];
}

// ---------------- layernorm -> fp16 ----------------
__global__ void ln_kernel(const float* __restrict__ x,
                          const float* __restrict__ scale, const float* __restrict__ bias,
                          __half* __restrict__ o) {
    __shared__ float s1[256], s2[256];
    int row = blockIdx.x, tid = threadIdx.x;
    const float* xr = x + (size_t)row * Ee;
    float sum = 0.f, sq = 0.f;
    for (int c = tid; c < Ee; c += 256) { float v = xr[c]; sum += v; sq += v * v; }
    s1[tid] = sum; s2[tid] = sq; __syncthreads();
    for (int s = 128; s > 0; s >>= 1) {
        if (tid < s) { s1[tid] += s1[tid+s]; s2[tid] += s2[tid+s]; }
        __syncthreads();
    }
    float mean = s1[0] * (1.0f / Ee);
    float var  = s2[0] * (1.0f / Ee) - mean * mean;
    float rstd = rsqrtf(var + 1e-5f);
    for (int c = tid; c < Ee; c += 256) {
        float v = (xr[c] - mean) * rstd * scale[c] + bias[c];
        o[(size_t)row * Ee + c] = __float2half(v);
    }
}

// ---------------- HMMA GEMM flags ----------------
#define FLAG_BIAS 1
#define FLAG_GELU 2
#define FLAG_RES  4
#define FLAG_F16OUT 8

__device__ __forceinline__ void epi_store(float v0, float v1, int row, int col, int N,
                                          const float* bias, const float* res,
                                          float* C, __half* Cf, int flags) {
    if (flags & FLAG_BIAS) {
        if (col < N)     v0 += bias[col];
        if (col + 1 < N) v1 += bias[col + 1];
    }
    if (flags & FLAG_GELU) {
        v0 = 0.5f * v0 * (1.0f + erff(v0 * 0.7071067811865476f));
        v1 = 0.5f * v1 * (1.0f + erff(v1 * 0.7071067811865476f));
    }
    size_t ci = (size_t)row * N + col;
    if (flags & FLAG_RES) {
        if (col < N)     v0 += res[ci];
        if (col + 1 < N) v1 += res[ci + 1];
    }
    if (flags & FLAG_F16OUT) {
        if (col < N)     Cf[ci]   = __float2half(v0);
        if (col + 1 < N) Cf[ci+1] = __float2half(v1);
    } else {
        if (col < N)     C[ci]   = v0;
        if (col + 1 < N) C[ci+1] = v1;
    }
}

#define NSTAGE 3
// BK=64: 128B rows, per-row XOR-16B swizzle (chunk ^ (row&7)); conflict-free ldsm.
#define SWZ(row, chunk) (((uint32_t)(row)) * 128u + ((uint32_t)((chunk) ^ ((row) & 7)) << 4))

// ======== WIDE: BM=128, BN=128, BK=64, 2 CTAs/SM ========
#define A_TILE_W (128 * 128)    // 16384
#define STAGE_W  (2 * A_TILE_W) // 32768
#define GEMM_SMEM_W (NSTAGE * STAGE_W)   // 98304

__global__ __launch_bounds__(256, 2)
void gemm_wide(const __half* __restrict__ A, const __half* __restrict__ W,
               const float* __restrict__ bias, const float* __restrict__ res,
               float* __restrict__ C, __half* __restrict__ Cf,
               int N, int K, int flags) {
    extern __shared__ char smem[];
    const uint32_t sb = smem_u32(smem);
    const int tid  = threadIdx.x;
    const int lane = tid & 31;
    const int wid  = tid >> 5;
    const int wm   = wid >> 2;           // 0..1 : 64-row band
    const int wn   = wid & 3;            // 0..3 : 32-col band
    const int bm   = blockIdx.x * 128;
    const int bn   = blockIdx.y * 128;

    float acc[4][4][4];
    #pragma unroll
    for (int i = 0; i < 4; i++)
        #pragma unroll
        for (int j = 0; j < 4; j++)
            #pragma unroll
            for (int r = 0; r < 4; r++) acc[i][j][r] = 0.f;

    const int nc = K >> 6;   // BK = 64

    auto load_stage = [&](int c, int stage) {
        const int k0 = c << 6;
        const uint32_t sdst = sb + stage * STAGE_W;
        #pragma unroll
        for (int it = 0; it < 8; it++) {      // 1024 A + 1024 W chunks of 16B
            int gi = it * 256 + tid;
            uint32_t dst; const __half* src;
            if (gi < 1024) {
                int row = gi >> 3, chunk = gi & 7;
                dst = sdst + SWZ(row, chunk);
                src = A + (size_t)(bm + row) * K + k0 + chunk * 8;
            } else {
                int li = gi - 1024;
                int row = li >> 3, chunk = li & 7;
                int gn = bn + row; if (gn > N - 1) gn = N - 1;
                dst = sdst + A_TILE_W + SWZ(row, chunk);
                src = W + (size_t)gn * K + k0 + chunk * 8;
            }
            cp16(dst, src);
        }
    };

    #pragma unroll
    for (int s = 0; s < NSTAGE - 1; s++) {
        if (s < nc) load_stage(s, s);
        CP_COMMIT();
    }

    for (int c = 0; c < nc; c++) {
        cp_wait<NSTAGE - 2>();
        __syncthreads();

        if (c + NSTAGE - 1 < nc) load_stage(c + NSTAGE - 1, (c + NSTAGE - 1) % NSTAGE);
        CP_COMMIT();

        const uint32_t st = sb + (c % NSTAGE) * STAGE_W;
        #pragma unroll
        for (int ks = 0; ks < 4; ks++) {      // 4 x k16 steps
            uint32_t fa[4][4], fb[4][2];
            #pragma unroll
            for (int p = 0; p < 2; p++) {
                int nrow = wn * 32 + p * 16 + (lane & 7) + 8 * (lane >> 4);
                int chunk = ks * 2 + ((lane >> 3) & 1);
                uint32_t r0,r1,r2,r3;
                ldsm_x4(st + A_TILE_W + SWZ(nrow, chunk), r0, r1, r2, r3);
                fb[2*p][0]=r0; fb[2*p][1]=r1; fb[2*p+1][0]=r2; fb[2*p+1][1]=r3;
            }
            #pragma unroll
            for (int i = 0; i < 4; i++) {
                int mrow = wm * 64 + i * 16 + (lane & 7) + 8 * ((lane >> 3) & 1);
                int chunk = ks * 2 + (lane >> 4);
                ldsm_x4(st + SWZ(mrow, chunk), fa[i][0], fa[i][1], fa[i][2], fa[i][3]);
            }
            #pragma unroll
            for (int i = 0; i < 4; i++)
                #pragma unroll
                for (int j = 0; j < 4; j++)
                    mma16816f(acc[i][j], fa[i], fb[j]);
        }
    }

    #pragma unroll
    for (int i = 0; i < 4; i++) {
        int row0 = bm + wm * 64 + i * 16 + (lane >> 2);
        #pragma unroll
        for (int j = 0; j < 4; j++) {
            int col = bn + wn * 32 + j * 8 + (lane & 3) * 2;
            #pragma unroll
            for (int half = 0; half < 2; half++)
                epi_store(acc[i][j][2*half], acc[i][j][2*half+1],
                          row0 + half * 8, col, N, bias, res, C, Cf, flags);
        }
    }
}

// ======== NARROW: BM=64, BN=64, BK=64, 3 CTAs/SM (N=768 GEMMs; grid 32x12) ========
#define A_TILE_N (64 * 128)     // 8192
#define STAGE_N  (2 * A_TILE_N) // 16384
#define GEMM_SMEM_N (NSTAGE * STAGE_N)   // 49152

__global__ __launch_bounds__(256, 3)
void gemm_n64(const __half* __restrict__ A, const __half* __restrict__ W,
              const float* __restrict__ bias, const float* __restrict__ res,
              float* __restrict__ C, __half* __restrict__ Cf,
              int N, int K, int flags) {
    extern __shared__ char smem[];
    const uint32_t sb = smem_u32(smem);
    const int tid  = threadIdx.x;
    const int lane = tid & 31;
    const int wid  = tid >> 5;
    const int wm   = wid >> 2;           // 0..1 : 32-row band
    const int wn   = wid & 3;            // 0..3 : 16-col band
    const int bm   = blockIdx.x * 64;
    const int bn   = blockIdx.y * 64;

    float acc[2][2][4];
    #pragma unroll
    for (int i = 0; i < 2; i++)
        #pragma unroll
        for (int j = 0; j < 2; j++)
            #pragma unroll
            for (int r = 0; r < 4; r++) acc[i][j][r] = 0.f;

    const int nc = K >> 6;

    auto load_stage = [&](int c, int stage) {
        const int k0 = c << 6;
        const uint32_t sdst = sb + stage * STAGE_N;
        #pragma unroll
        for (int it = 0; it < 4; it++) {      // 512 A + 512 W chunks
            int gi = it * 256 + tid;
            uint32_t dst; const __half* src;
            if (gi < 512) {
                int row = gi >> 3, chunk = gi & 7;
                dst = sdst + SWZ(row, chunk);
                src = A + (size_t)(bm + row) * K + k0 + chunk * 8;
            } else {
                int li = gi - 512;
                int row = li >> 3, chunk = li & 7;
                int gn = bn + row; if (gn > N - 1) gn = N - 1;
                dst = sdst + A_TILE_N + SWZ(row, chunk);
                src = W + (size_t)gn * K + k0 + chunk * 8;
            }
            cp16(dst, src);
        }
    };

    #pragma unroll
    for (int s = 0; s < NSTAGE - 1; s++) {
        if (s < nc) load_stage(s, s);
        CP_COMMIT();
    }

    for (int c = 0; c < nc; c++) {
        cp_wait<NSTAGE - 2>();
        __syncthreads();

        if (c + NSTAGE - 1 < nc) load_stage(c + NSTAGE - 1, (c + NSTAGE - 1) % NSTAGE);
        CP_COMMIT();

        const uint32_t st = sb + (c % NSTAGE) * STAGE_N;
        #pragma unroll
        for (int ks = 0; ks < 4; ks++) {
            uint32_t fa[2][4], fb[2][2];
            {
                int nrow = wn * 16 + (lane & 7) + 8 * (lane >> 4);
                int chunk = ks * 2 + ((lane >> 3) & 1);
                uint32_t r0,r1,r2,r3;
                ldsm_x4(st + A_TILE_N + SWZ(nrow, chunk), r0, r1, r2, r3);
                fb[0][0]=r0; fb[0][1]=r1; fb[1][0]=r2; fb[1][1]=r3;
            }
            #pragma unroll
            for (int i = 0; i < 2; i++) {
                int mrow = wm * 32 + i * 16 + (lane & 7) + 8 * ((lane >> 3) & 1);
                int chunk = ks * 2 + (lane >> 4);
                ldsm_x4(st + SWZ(mrow, chunk), fa[i][0], fa[i][1], fa[i][2], fa[i][3]);
            }
            #pragma unroll
            for (int i = 0; i < 2; i++)
                #pragma unroll
                for (int j = 0; j < 2; j++)
                    mma16816f(acc[i][j], fa[i], fb[j]);
        }
    }

    #pragma unroll
    for (int i = 0; i < 2; i++) {
        int row0 = bm + wm * 32 + i * 16 + (lane >> 2);
        #pragma unroll
        for (int j = 0; j < 2; j++) {
            int col = bn + wn * 16 + j * 8 + (lane & 3) * 2;
            #pragma unroll
            for (int half = 0; half < 2; half++)
                epi_store(acc[i][j][2*half], acc[i][j][2*half+1],
                          row0 + half * 8, col, N, bias, res, C, Cf, flags);
        }
    }
}

// ---------------- flash attention: 64 queries per block ----------------
#define ATT_SMEM (4 * 64 * 68 * 4)
__global__ __launch_bounds__(256)
void attn_flash(const float* __restrict__ qkv, __half* __restrict__ o) {
    extern __shared__ float sm[];
    float* Qs = sm;
    float* Ks = sm + 64 * 68;
    float* Vs = sm + 2 * 64 * 68;
    float* Ps = sm + 3 * 64 * 68;

    const int qt = blockIdx.x, h = blockIdx.y, b = blockIdx.z;
    const int tid = threadIdx.x;
    const int q   = tid >> 2;
    const int sg  = tid & 3;
    const int q_glob = qt * 64 + q;

    for (int i = tid; i < 64 * 16; i += 256) {
        int r = i >> 4, c4 = (i & 15);
        float4 v = *(const float4*)&qkv[((size_t)(b*Tt + qt*64 + r))*(3*Ee) + h*HDd + c4*4];
        *(float4*)&Qs[r * 68 + c4 * 4] = v;
    }

    float m_run = -1e30f, l_run = 0.f;
    float out[16];
    #pragma unroll
    for (int i = 0; i < 16; i++) out[i] = 0.f;
    __syncthreads();

    for (int kt = 0; kt <= qt; kt++) {
        for (int i = tid; i < 64 * 16; i += 256) {
            int r = i >> 4, c4 = (i & 15);
            size_t base = ((size_t)(b*Tt + kt*64 + r)) * (3*Ee) + h*HDd;
            float4 kv = *(const float4*)&qkv[base + Ee   + c4*4];
            float4 vv = *(const float4*)&qkv[base + 2*Ee + c4*4];
            *(float4*)&Ks[r * 68 + (c4 ^ ((r >> 4) & 3)) * 4] = kv;
            *(float4*)&Vs[r * 68 + c4 * 4] = vv;
        }
        __syncthreads();

        float s[16];
        #pragma unroll
        for (int kk = 0; kk < 16; kk++) s[kk] = 0.f;
        #pragma unroll
        for (int d4 = 0; d4 < 16; d4++) {
            float4 qv = *(const float4*)&Qs[q * 68 + d4 * 4];
            #pragma unroll
            for (int kk = 0; kk < 16; kk++) {
                int krow = sg * 16 + kk;
                float4 kv = *(const float4*)&Ks[krow * 68 + (d4 ^ sg) * 4];
                s[kk] = fmaf(qv.x, kv.x, fmaf(qv.y, kv.y, fmaf(qv.z, kv.z, fmaf(qv.w, kv.w, s[kk]))));
            }
        }
        const int k0g = kt * 64 + sg * 16;
        float lmax = -1e30f;
        #pragma unroll
        for (int kk = 0; kk < 16; kk++) {
            s[kk] *= 0.125f;
            if (k0g + kk > q_glob) s[kk] = -1e30f;
            lmax = fmaxf(lmax, s[kk]);
        }
        lmax = fmaxf(lmax, __shfl_xor_sync(0xFFFFFFFFu, lmax, 1));
        lmax = fmaxf(lmax, __shfl_xor_sync(0xFFFFFFFFu, lmax, 2));
        float mnew = fmaxf(m_run, lmax);
        float f = __expf(m_run - mnew);
        l_run *= f;
        #pragma unroll
        for (int i = 0; i < 16; i++) out[i] *= f;
        float psum = 0.f;
        #pragma unroll
        for (int kk = 0; kk < 16; kk++) {
            float p = __expf(s[kk] - mnew);
            psum += p;
            Ps[q * 68 + sg * 16 + kk] = p;
        }
        psum += __shfl_xor_sync(0xFFFFFFFFu, psum, 1);
        psum += __shfl_xor_sync(0xFFFFFFFFu, psum, 2);
        l_run += psum;
        m_run = mnew;
        __syncwarp();

        for (int k = 0; k < 64; k++) {
            float p = Ps[q * 68 + k];
            #pragma unroll
            for (int d4i = 0; d4i < 4; d4i++) {
                float4 vv = *(const float4*)&Vs[k * 68 + sg * 16 + d4i * 4];
                out[d4i*4+0] = fmaf(p, vv.x, out[d4i*4+0]);
                out[d4i*4+1] = fmaf(p, vv.y, out[d4i*4+1]);
                out[d4i*4+2] = fmaf(p, vv.z, out[d4i*4+2]);
                out[d4i*4+3] = fmaf(p, vv.w, out[d4i*4+3]);
            }
        }
        __syncthreads();
    }

    float inv = 1.0f / l_run;
    size_t obase = ((size_t)(b*Tt + q_glob)) * Ee + h * HDd + sg * 16;
    #pragma unroll
    for (int i = 0; i < 16; i++)
        o[obase + i] = __float2half(out[i] * inv);
}

// ---------------- launcher ----------------
static void run_wide(const __half* A, const __half* W,
                     const float* bias, const float* res,
                     float* C, __half* Cf, int N, int K, int flags) {
    dim3 g(BT / 128, (N + 127) / 128);
    gemm_wide<<<g, 256, GEMM_SMEM_W>>>(A, W, bias, res, C, Cf, N, K, flags);
}
static void run_narrow(const __half* A, const __half* W,
                       const float* bias, const float* res,
                       float* C, __half* Cf, int N, int K, int flags) {
    dim3 g(BT / 64, (N + 63) / 64);
    gemm_n64<<<g, 256, GEMM_SMEM_N>>>(A, W, bias, res, C, Cf, N, K, flags);
}

extern "C" void kernel_launch(void* const* d_in, const int* in_sizes, int n_in,
                              void* d_out, int out_size) {
    const int*   input_ids = (const int*)  d_in[0];
    const float* tok_emb   = (const float*)d_in[1];
    const float* pos_emb   = (const float*)d_in[2];
    const float* ln1_scale = (const float*)d_in[3];
    const float* ln1_bias  = (const float*)d_in[4];
    const float* qkv_w     = (const float*)d_in[5];
    const float* out_w     = (const float*)d_in[6];
    const float* ln2_scale = (const float*)d_in[7];
    const float* ln2_bias  = (const float*)d_in[8];
    const float* fc1_w     = (const float*)d_in[9];
    const float* fc1_b     = (const float*)d_in[10];
    const float* fc2_w     = (const float*)d_in[11];
    const float* fc2_b     = (const float*)d_in[12];
    const float* lnf_scale = (const float*)d_in[13];
    const float* lnf_bias  = (const float*)d_in[14];
    float* logits = (float*)d_out;

    cudaFuncSetAttribute((const void*)gemm_wide,  cudaFuncAttributeMaxDynamicSharedMemorySize, GEMM_SMEM_W);
    cudaFuncSetAttribute((const void*)gemm_n64,   cudaFuncAttributeMaxDynamicSharedMemorySize, GEMM_SMEM_N);
    cudaFuncSetAttribute((const void*)attn_flash, cudaFuncAttributeMaxDynamicSharedMemorySize, ATT_SMEM);

    float *x, *qkv;
    __half *h, *at, *f, *qw, *ow, *f1, *f2, *te;
    cudaGetSymbolAddress((void**)&x,   g_x);
    cudaGetSymbolAddress((void**)&qkv, g_qkv);
    cudaGetSymbolAddress((void**)&h,   g_h);
    cudaGetSymbolAddress((void**)&at,  g_at);
    cudaGetSymbolAddress((void**)&f,   g_f);
    cudaGetSymbolAddress((void**)&qw,  g_qw);  cudaGetSymbolAddress((void**)&ow,  g_ow);
    cudaGetSymbolAddress((void**)&f1,  g_f1);  cudaGetSymbolAddress((void**)&f2,  g_f2);
    cudaGetSymbolAddress((void**)&te,  g_te);

    // single merged weight conversion
    conv_all_kernel<<<(C_TOT + 255) / 256, 256>>>(qkv_w, out_w, fc1_w, fc2_w, tok_emb,
                                                  qw, ow, f1, f2, te);

    embed_kernel<<<(BT * Ee + 255) / 256, 256>>>(input_ids, tok_emb, pos_emb, x);

    for (int l = 0; l < Ll; l++) {
        // attention block (pre-norm)
        ln_kernel<<<BT, 256>>>(x, ln1_scale + l * Ee, ln1_bias + l * Ee, h);
        run_wide(h, qw + (size_t)l * 3 * Ee * Ee,
                 nullptr, nullptr, qkv, nullptr, 3 * Ee, Ee, 0);
        attn_flash<<<dim3(Tt/64, NHh, Bb), 256, ATT_SMEM>>>(qkv, at);
        run_narrow(at, ow + (size_t)l * Ee * Ee,
                   nullptr, x, x, nullptr, Ee, Ee, FLAG_RES);
        // FFN block (pre-norm)
        ln_kernel<<<BT, 256>>>(x, ln2_scale + l * Ee, ln2_bias + l * Ee, h);
        run_wide(h, f1 + (size_t)l * FFf * Ee,
                 fc1_b + (size_t)l * FFf, nullptr, nullptr, f,
                 FFf, Ee, FLAG_BIAS | FLAG_GELU | FLAG_F16OUT);
        run_narrow(f, f2 + (size_t)l * Ee * FFf,
                   fc2_b + (size_t)l * Ee, x, x, nullptr,
                   Ee, FFf, FLAG_BIAS | FLAG_RES);
    }

    // final layernorm + tied LM head
    ln_kernel<<<BT, 256>>>(x, lnf_scale, lnf_bias, h);
    run_wide(h, te, nullptr, nullptr, logits, nullptr, Vv, Ee, 0);
}

// round 16
// speedup vs baseline: 2.8102x; 2.3578x over previous
#include <cuda_runtime.h>
#include <cuda_bf16.h>
#include <cuda_fp16.h>
#include <cstdint>
#include <math.h>

// ---------------- problem constants ----------------
#define Vv 50257
#define Ee 768
#define NHh 12
#define HDd 64
#define Ll 4
#define Tt 1024
#define Bb 2
#define FFf 3072
#define BT (Bb*Tt)            // 2048 rows

// ---------------- scratch (static, no allocs) ----------------
__device__ float g_x  [BT * Ee];                 // residual stream (fp32)
__device__ __half g_qkvh[BT * 3*Ee];             // qkv projection (fp16)
__device__ __half g_h [BT*Ee];                   // LN output fp16
__device__ __half g_at[BT*Ee];                   // attn output fp16
__device__ __half g_f [BT*FFf];                  // ffn hidden fp16
// weights, single fp16
__device__ __half g_qw[Ll*3*Ee*Ee];
__device__ __half g_ow[Ll*Ee*Ee];
__device__ __half g_f1[Ll*FFf*Ee];
__device__ __half g_f2[Ll*Ee*FFf];
__device__ __half g_te[Vv*Ee];

__device__ __forceinline__ uint32_t smem_u32(const void* p) {
    uint32_t a;
    asm("{ .reg .u64 t; cvta.to.shared.u64 t, %1; cvt.u32.u64 %0, t; }" : "=r"(a) : "l"(p));
    return a;
}
__device__ __forceinline__ void cp16(uint32_t dst, const void* src) {
    asm volatile("cp.async.cg.shared.global [%0], [%1], 16;" :: "r"(dst), "l"(src));
}
#define CP_COMMIT() asm volatile("cp.async.commit_group;" ::: "memory")
template<int N> __device__ __forceinline__ void cp_wait() {
    asm volatile("cp.async.wait_group %0;" :: "n"(N) : "memory");
}

__device__ __forceinline__ void ldsm_x4(uint32_t a, uint32_t& r0, uint32_t& r1, uint32_t& r2, uint32_t& r3) {
    asm volatile("ldmatrix.sync.aligned.m8n8.x4.shared.b16 {%0,%1,%2,%3}, [%4];"
                 : "=r"(r0), "=r"(r1), "=r"(r2), "=r"(r3) : "r"(a));
}
__device__ __forceinline__ void ldsm_x4t(uint32_t a, uint32_t& r0, uint32_t& r1, uint32_t& r2, uint32_t& r3) {
    asm volatile("ldmatrix.sync.aligned.m8n8.x4.trans.shared.b16 {%0,%1,%2,%3}, [%4];"
                 : "=r"(r0), "=r"(r1), "=r"(r2), "=r"(r3) : "r"(a));
}
__device__ __forceinline__ void mma16816f(float* d, const uint32_t* a, const uint32_t* b) {
    asm volatile("mma.sync.aligned.m16n8k16.row.col.f32.f16.f16.f32 "
                 "{%0,%1,%2,%3}, {%4,%5,%6,%7}, {%8,%9}, {%0,%1,%2,%3};"
                 : "+f"(d[0]), "+f"(d[1]), "+f"(d[2]), "+f"(d[3])
                 : "r"(a[0]), "r"(a[1]), "r"(a[2]), "r"(a[3]), "r"(b[0]), "r"(b[1]));
}

// ---------------- merged fp32 -> fp16 weight conversion (one launch) ----------------
#define C_QW (Ll*3*Ee*Ee/4)
#define C_OW (Ll*Ee*Ee/4)
#define C_F1 (Ll*FFf*Ee/4)
#define C_F2 (Ll*Ee*FFf/4)
#define C_TE (Vv*Ee/4)
#define C_TOT (C_QW + C_OW + C_F1 + C_F2 + C_TE)

__global__ void conv_all_kernel(const float* __restrict__ qkv_w, const float* __restrict__ out_w,
                                const float* __restrict__ fc1_w, const float* __restrict__ fc2_w,
                                const float* __restrict__ tok_emb,
                                __half* __restrict__ qw, __half* __restrict__ ow,
                                __half* __restrict__ f1, __half* __restrict__ f2,
                                __half* __restrict__ te) {
    int i = blockIdx.x * blockDim.x + threadIdx.x;
    if (i >= C_TOT) return;
    const float* src; __half* dst; int off = i;
    if (off < C_QW)                        { src = qkv_w;  dst = qw; }
    else if ((off -= C_QW) < C_OW)         { src = out_w;  dst = ow; }
    else if ((off -= C_OW) < C_F1)         { src = fc1_w;  dst = f1; }
    else if ((off -= C_F1) < C_F2)         { src = fc2_w;  dst = f2; }
    else      { off -= C_F2;                 src = tok_emb; dst = te; }
    float4 v = ((const float4*)src)[off];
    __half2 a, b;
    a.x = __float2half(v.x); a.y = __float2half(v.y);
    b.x = __float2half(v.z); b.y = __float2half(v.w);
    ((__half2*)dst)[2*off]   = a;
    ((__half2*)dst)[2*off+1] = b;
}

// ---------------- embedding ----------------
__global__ void embed_kernel(const int* __restrict__ ids, const float* __restrict__ tok,
                             const float* __restrict__ pos, float* __restrict__ out) {
    int i = blockIdx.x * blockDim.x + threadIdx.x;
    if (i >= BT * Ee) return;
    int e = i % Ee, row = i / Ee, t = row % Tt;
    out[i] = tok[(size_t)ids[row] * Ee + e] + pos[t * Ee + e];
}

// ---------------- layernorm -> fp16 ----------------
__global__ void ln_kernel(const float* __restrict__ x,
                          const float* __restrict__ scale, const float* __restrict__ bias,
                          __half* __restrict__ o) {
    __shared__ float s1[256], s2[256];
    int row = blockIdx.x, tid = threadIdx.x;
    const float* xr = x + (size_t)row * Ee;
    float sum = 0.f, sq = 0.f;
    for (int c = tid; c < Ee; c += 256) { float v = xr[c]; sum += v; sq += v * v; }
    s1[tid] = sum; s2[tid] = sq; __syncthreads();
    for (int s = 128; s > 0; s >>= 1) {
        if (tid < s) { s1[tid] += s1[tid+s]; s2[tid] += s2[tid+s]; }
        __syncthreads();
    }
    float mean = s1[0] * (1.0f / Ee);
    float var  = s2[0] * (1.0f / Ee) - mean * mean;
    float rstd = rsqrtf(var + 1e-5f);
    for (int c = tid; c < Ee; c += 256) {
        float v = (xr[c] - mean) * rstd * scale[c] + bias[c];
        o[(size_t)row * Ee + c] = __float2half(v);
    }
}

// ---------------- HMMA GEMM flags ----------------
#define FLAG_BIAS 1
#define FLAG_GELU 2
#define FLAG_RES  4
#define FLAG_F16OUT 8

__device__ __forceinline__ void epi_store(float v0, float v1, int row, int col, int N,
                                          const float* bias, const float* res,
                                          float* C, __half* Cf, int flags) {
    if (flags & FLAG_BIAS) {
        if (col < N)     v0 += bias[col];
        if (col + 1 < N) v1 += bias[col + 1];
    }
    if (flags & FLAG_GELU) {
        v0 = 0.5f * v0 * (1.0f + erff(v0 * 0.7071067811865476f));
        v1 = 0.5f * v1 * (1.0f + erff(v1 * 0.7071067811865476f));
    }
    size_t ci = (size_t)row * N + col;
    if (flags & FLAG_RES) {
        if (col < N)     v0 += res[ci];
        if (col + 1 < N) v1 += res[ci + 1];
    }
    if (flags & FLAG_F16OUT) {
        if (col < N)     Cf[ci]   = __float2half(v0);
        if (col + 1 < N) Cf[ci+1] = __float2half(v1);
    } else {
        if (col < N)     C[ci]   = v0;
        if (col + 1 < N) C[ci+1] = v1;
    }
}

#define NSTAGE 3
// BK=64: 128B rows, per-row XOR-16B swizzle (chunk ^ (row&7)); conflict-free ldsm.
#define SWZ(row, chunk) (((uint32_t)(row)) * 128u + ((uint32_t)((chunk) ^ ((row) & 7)) << 4))

// ======== WIDE: BM=128, BN=128, BK=64, 2 CTAs/SM ========
#define A_TILE_W (128 * 128)    // 16384
#define STAGE_W  (2 * A_TILE_W) // 32768
#define GEMM_SMEM_W (NSTAGE * STAGE_W)   // 98304

__global__ __launch_bounds__(256, 2)
void gemm_wide(const __half* __restrict__ A, const __half* __restrict__ W,
               const float* __restrict__ bias, const float* __restrict__ res,
               float* __restrict__ C, __half* __restrict__ Cf,
               int N, int K, int flags) {
    extern __shared__ char smem[];
    const uint32_t sb = smem_u32(smem);
    const int tid  = threadIdx.x;
    const int lane = tid & 31;
    const int wid  = tid >> 5;
    const int wm   = wid >> 2;
    const int wn   = wid & 3;
    const int bm   = blockIdx.x * 128;
    const int bn   = blockIdx.y * 128;

    float acc[4][4][4];
    #pragma unroll
    for (int i = 0; i < 4; i++)
        #pragma unroll
        for (int j = 0; j < 4; j++)
            #pragma unroll
            for (int r = 0; r < 4; r++) acc[i][j][r] = 0.f;

    const int nc = K >> 6;   // BK = 64

    auto load_stage = [&](int c, int stage) {
        const int k0 = c << 6;
        const uint32_t sdst = sb + stage * STAGE_W;
        #pragma unroll
        for (int it = 0; it < 8; it++) {
            int gi = it * 256 + tid;
            uint32_t dst; const __half* src;
            if (gi < 1024) {
                int row = gi >> 3, chunk = gi & 7;
                dst = sdst + SWZ(row, chunk);
                src = A + (size_t)(bm + row) * K + k0 + chunk * 8;
            } else {
                int li = gi - 1024;
                int row = li >> 3, chunk = li & 7;
                int gn = bn + row; if (gn > N - 1) gn = N - 1;
                dst = sdst + A_TILE_W + SWZ(row, chunk);
                src = W + (size_t)gn * K + k0 + chunk * 8;
            }
            cp16(dst, src);
        }
    };

    #pragma unroll
    for (int s = 0; s < NSTAGE - 1; s++) {
        if (s < nc) load_stage(s, s);
        CP_COMMIT();
    }

    for (int c = 0; c < nc; c++) {
        cp_wait<NSTAGE - 2>();
        __syncthreads();

        if (c + NSTAGE - 1 < nc) load_stage(c + NSTAGE - 1, (c + NSTAGE - 1) % NSTAGE);
        CP_COMMIT();

        const uint32_t st = sb + (c % NSTAGE) * STAGE_W;
        #pragma unroll
        for (int ks = 0; ks < 4; ks++) {
            uint32_t fa[4][4], fb[4][2];
            #pragma unroll
            for (int p = 0; p < 2; p++) {
                int nrow = wn * 32 + p * 16 + (lane & 7) + 8 * (lane >> 4);
                int chunk = ks * 2 + ((lane >> 3) & 1);
                uint32_t r0,r1,r2,r3;
                ldsm_x4(st + A_TILE_W + SWZ(nrow, chunk), r0, r1, r2, r3);
                fb[2*p][0]=r0; fb[2*p][1]=r1; fb[2*p+1][0]=r2; fb[2*p+1][1]=r3;
            }
            #pragma unroll
            for (int i = 0; i < 4; i++) {
                int mrow = wm * 64 + i * 16 + (lane & 7) + 8 * ((lane >> 3) & 1);
                int chunk = ks * 2 + (lane >> 4);
                ldsm_x4(st + SWZ(mrow, chunk), fa[i][0], fa[i][1], fa[i][2], fa[i][3]);
            }
            #pragma unroll
            for (int i = 0; i < 4; i++)
                #pragma unroll
                for (int j = 0; j < 4; j++)
                    mma16816f(acc[i][j], fa[i], fb[j]);
        }
    }

    #pragma unroll
    for (int i = 0; i < 4; i++) {
        int row0 = bm + wm * 64 + i * 16 + (lane >> 2);
        #pragma unroll
        for (int j = 0; j < 4; j++) {
            int col = bn + wn * 32 + j * 8 + (lane & 3) * 2;
            #pragma unroll
            for (int half = 0; half < 2; half++)
                epi_store(acc[i][j][2*half], acc[i][j][2*half+1],
                          row0 + half * 8, col, N, bias, res, C, Cf, flags);
        }
    }
}

// ======== NARROW: BM=64, BN=64, BK=64, 3 CTAs/SM ========
#define A_TILE_N (64 * 128)     // 8192
#define STAGE_N  (2 * A_TILE_N) // 16384
#define GEMM_SMEM_N (NSTAGE * STAGE_N)   // 49152

__global__ __launch_bounds__(256, 3)
void gemm_n64(const __half* __restrict__ A, const __half* __restrict__ W,
              const float* __restrict__ bias, const float* __restrict__ res,
              float* __restrict__ C, __half* __restrict__ Cf,
              int N, int K, int flags) {
    extern __shared__ char smem[];
    const uint32_t sb = smem_u32(smem);
    const int tid  = threadIdx.x;
    const int lane = tid & 31;
    const int wid  = tid >> 5;
    const int wm   = wid >> 2;
    const int wn   = wid & 3;
    const int bm   = blockIdx.x * 64;
    const int bn   = blockIdx.y * 64;

    float acc[2][2][4];
    #pragma unroll
    for (int i = 0; i < 2; i++)
        #pragma unroll
        for (int j = 0; j < 2; j++)
            #pragma unroll
            for (int r = 0; r < 4; r++) acc[i][j][r] = 0.f;

    const int nc = K >> 6;

    auto load_stage = [&](int c, int stage) {
        const int k0 = c << 6;
        const uint32_t sdst = sb + stage * STAGE_N;
        #pragma unroll
        for (int it = 0; it < 4; it++) {
            int gi = it * 256 + tid;
            uint32_t dst; const __half* src;
            if (gi < 512) {
                int row = gi >> 3, chunk = gi & 7;
                dst = sdst + SWZ(row, chunk);
                src = A + (size_t)(bm + row) * K + k0 + chunk * 8;
            } else {
                int li = gi - 512;
                int row = li >> 3, chunk = li & 7;
                int gn = bn + row; if (gn > N - 1) gn = N - 1;
                dst = sdst + A_TILE_N + SWZ(row, chunk);
                src = W + (size_t)gn * K + k0 + chunk * 8;
            }
            cp16(dst, src);
        }
    };

    #pragma unroll
    for (int s = 0; s < NSTAGE - 1; s++) {
        if (s < nc) load_stage(s, s);
        CP_COMMIT();
    }

    for (int c = 0; c < nc; c++) {
        cp_wait<NSTAGE - 2>();
        __syncthreads();

        if (c + NSTAGE - 1 < nc) load_stage(c + NSTAGE - 1, (c + NSTAGE - 1) % NSTAGE);
        CP_COMMIT();

        const uint32_t st = sb + (c % NSTAGE) * STAGE_N;
        #pragma unroll
        for (int ks = 0; ks < 4; ks++) {
            uint32_t fa[2][4], fb[2][2];
            {
                int nrow = wn * 16 + (lane & 7) + 8 * (lane >> 4);
                int chunk = ks * 2 + ((lane >> 3) & 1);
                uint32_t r0,r1,r2,r3;
                ldsm_x4(st + A_TILE_N + SWZ(nrow, chunk), r0, r1, r2, r3);
                fb[0][0]=r0; fb[0][1]=r1; fb[1][0]=r2; fb[1][1]=r3;
            }
            #pragma unroll
            for (int i = 0; i < 2; i++) {
                int mrow = wm * 32 + i * 16 + (lane & 7) + 8 * ((lane >> 3) & 1);
                int chunk = ks * 2 + (lane >> 4);
                ldsm_x4(st + SWZ(mrow, chunk), fa[i][0], fa[i][1], fa[i][2], fa[i][3]);
            }
            #pragma unroll
            for (int i = 0; i < 2; i++)
                #pragma unroll
                for (int j = 0; j < 2; j++)
                    mma16816f(acc[i][j], fa[i], fb[j]);
        }
    }

    #pragma unroll
    for (int i = 0; i < 2; i++) {
        int row0 = bm + wm * 32 + i * 16 + (lane >> 2);
        #pragma unroll
        for (int j = 0; j < 2; j++) {
            int col = bn + wn * 16 + j * 8 + (lane & 3) * 2;
            #pragma unroll
            for (int half = 0; half < 2; half++)
                epi_store(acc[i][j][2*half], acc[i][j][2*half+1],
                          row0 + half * 8, col, N, bias, res, C, Cf, flags);
        }
    }
}

// ---------------- tensor-core flash attention ----------------
// grid (T/64, NH, B), 128 threads (4 warps, each owns 16 q rows).
__global__ __launch_bounds__(128)
void attn_tc(const __half* __restrict__ qkv, __half* __restrict__ o) {
    __shared__ __half Qs[64 * 64], Ks[64 * 64], Vs[64 * 64];
    const int qt = blockIdx.x, h = blockIdx.y, b = blockIdx.z;
    const int tid = threadIdx.x;
    const int lane = tid & 31;
    const int w = tid >> 5;
    const uint32_t qb = smem_u32(Qs), kb = smem_u32(Ks), vb = smem_u32(Vs);

    // load Q tile (64 rows x 128B, swizzled)
    for (int i = tid; i < 512; i += 128) {
        int r = i >> 3, ch = i & 7;
        cp16(qb + SWZ(r, ch),
             qkv + ((size_t)(b * Tt + qt * 64 + r)) * (3 * Ee) + h * HDd + ch * 8);
    }
    CP_COMMIT();

    float m_run[2] = {-1e30f, -1e30f}, l_run[2] = {0.f, 0.f};
    float oacc[8][4];
    #pragma unroll
    for (int t = 0; t < 8; t++)
        #pragma unroll
        for (int r = 0; r < 4; r++) oacc[t][r] = 0.f;

    const int rowA = qt * 64 + w * 16 + (lane >> 2);   // global q row (and rowA+8)

    for (int kt = 0; kt <= qt; kt++) {
        for (int i = tid; i < 512; i += 128) {
            int r = i >> 3, ch = i & 7;
            size_t base = ((size_t)(b * Tt + kt * 64 + r)) * (3 * Ee) + h * HDd;
            cp16(kb + SWZ(r, ch), qkv + base + Ee + ch * 8);
            cp16(vb + SWZ(r, ch), qkv + base + 2 * Ee + ch * 8);
        }
        CP_COMMIT();
        cp_wait<0>();
        __syncthreads();

        // ---- S = Q @ K^T (fp32 acc) ----
        float sacc[8][4];
        #pragma unroll
        for (int t = 0; t < 8; t++)
            #pragma unroll
            for (int r = 0; r < 4; r++) sacc[t][r] = 0.f;
        #pragma unroll
        for (int ks = 0; ks < 4; ks++) {
            uint32_t fa[4], fb[8][2];
            {
                int mrow = w * 16 + (lane & 7) + 8 * ((lane >> 3) & 1);
                int chunk = ks * 2 + (lane >> 4);
                ldsm_x4(qb + SWZ(mrow, chunk), fa[0], fa[1], fa[2], fa[3]);
            }
            #pragma unroll
            for (int p = 0; p < 4; p++) {
                int nrow = p * 16 + (lane & 7) + 8 * (lane >> 4);
                int chunk = ks * 2 + ((lane >> 3) & 1);
                uint32_t r0,r1,r2,r3;
                ldsm_x4(kb + SWZ(nrow, chunk), r0, r1, r2, r3);
                fb[2*p][0]=r0; fb[2*p][1]=r1; fb[2*p+1][0]=r2; fb[2*p+1][1]=r3;
            }
            #pragma unroll
            for (int t = 0; t < 8; t++)
                mma16816f(sacc[t], fa, fb[t]);
        }

        // ---- scale + causal mask ----
        #pragma unroll
        for (int t = 0; t < 8; t++) {
            int colg = kt * 64 + t * 8 + (lane & 3) * 2;
            #pragma unroll
            for (int r = 0; r < 4; r++) sacc[t][r] *= 0.125f;
            if (kt == qt) {
                if (colg     > rowA)     sacc[t][0] = -1e30f;
                if (colg + 1 > rowA)     sacc[t][1] = -1e30f;
                if (colg     > rowA + 8) sacc[t][2] = -1e30f;
                if (colg + 1 > rowA + 8) sacc[t][3] = -1e30f;
            }
        }

        // ---- online softmax (rows rowA, rowA+8) ----
        float mA = -1e30f, mB = -1e30f;
        #pragma unroll
        for (int t = 0; t < 8; t++) {
            mA = fmaxf(mA, fmaxf(sacc[t][0], sacc[t][1]));
            mB = fmaxf(mB, fmaxf(sacc[t][2], sacc[t][3]));
        }
        mA = fmaxf(mA, __shfl_xor_sync(0xFFFFFFFFu, mA, 1));
        mA = fmaxf(mA, __shfl_xor_sync(0xFFFFFFFFu, mA, 2));
        mB = fmaxf(mB, __shfl_xor_sync(0xFFFFFFFFu, mB, 1));
        mB = fmaxf(mB, __shfl_xor_sync(0xFFFFFFFFu, mB, 2));
        float mnA = fmaxf(m_run[0], mA), mnB = fmaxf(m_run[1], mB);
        float fA = __expf(m_run[0] - mnA), fB = __expf(m_run[1] - mnB);
        float psA = 0.f, psB = 0.f;
        #pragma unroll
        for (int t = 0; t < 8; t++) {
            sacc[t][0] = __expf(sacc[t][0] - mnA);
            sacc[t][1] = __expf(sacc[t][1] - mnA);
            sacc[t][2] = __expf(sacc[t][2] - mnB);
            sacc[t][3] = __expf(sacc[t][3] - mnB);
            psA += sacc[t][0] + sacc[t][1];
            psB += sacc[t][2] + sacc[t][3];
        }
        psA += __shfl_xor_sync(0xFFFFFFFFu, psA, 1);
        psA += __shfl_xor_sync(0xFFFFFFFFu, psA, 2);
        psB += __shfl_xor_sync(0xFFFFFFFFu, psB, 1);
        psB += __shfl_xor_sync(0xFFFFFFFFu, psB, 2);
        l_run[0] = l_run[0] * fA + psA;
        l_run[1] = l_run[1] * fB + psB;
        m_run[0] = mnA; m_run[1] = mnB;
        #pragma unroll
        for (int t = 0; t < 8; t++) {
            oacc[t][0] *= fA; oacc[t][1] *= fA;
            oacc[t][2] *= fB; oacc[t][3] *= fB;
        }

        // ---- O += P @ V (P from registers; V via ldsm.trans) ----
        #pragma unroll
        for (int ks = 0; ks < 4; ks++) {
            uint32_t pa[4];
            {
                __half2 h0 = __floats2half2_rn(sacc[2*ks][0],   sacc[2*ks][1]);
                __half2 h1 = __floats2half2_rn(sacc[2*ks][2],   sacc[2*ks][3]);
                __half2 h2 = __floats2half2_rn(sacc[2*ks+1][0], sacc[2*ks+1][1]);
                __half2 h3 = __floats2half2_rn(sacc[2*ks+1][2], sacc[2*ks+1][3]);
                pa[0] = *(uint32_t*)&h0; pa[1] = *(uint32_t*)&h1;
                pa[2] = *(uint32_t*)&h2; pa[3] = *(uint32_t*)&h3;
            }
            #pragma unroll
            for (int dp = 0; dp < 4; dp++) {
                int vrow = ks * 16 + (lane & 7) + 8 * ((lane >> 3) & 1);
                int chunk = 2 * dp + (lane >> 4);
                uint32_t r0,r1,r2,r3;
                ldsm_x4t(vb + SWZ(vrow, chunk), r0, r1, r2, r3);
                uint32_t b0[2] = {r0, r1}, b1[2] = {r2, r3};
                mma16816f(oacc[2*dp],     pa, b0);
                mma16816f(oacc[2*dp + 1], pa, b1);
            }
        }
        __syncthreads();   // before next kt overwrites K/V
    }

    float invA = 1.0f / l_run[0], invB = 1.0f / l_run[1];
    size_t baseA = ((size_t)(b * Tt + rowA)) * Ee + h * HDd;
    size_t baseB = ((size_t)(b * Tt + rowA + 8)) * Ee + h * HDd;
    #pragma unroll
    for (int t = 0; t < 8; t++) {
        int col = t * 8 + (lane & 3) * 2;
        __half2 va = __floats2half2_rn(oacc[t][0] * invA, oacc[t][1] * invA);
        __half2 vb2 = __floats2half2_rn(oacc[t][2] * invB, oacc[t][3] * invB);
        *(__half2*)(o + baseA + col) = va;
        *(__half2*)(o + baseB + col) = vb2;
    }
}

// ---------------- launcher ----------------
static void run_wide(const __half* A, const __half* W,
                     const float* bias, const float* res,
                     float* C, __half* Cf, int N, int K, int flags) {
    dim3 g(BT / 128, (N + 127) / 128);
    gemm_wide<<<g, 256, GEMM_SMEM_W>>>(A, W, bias, res, C, Cf, N, K, flags);
}
static void run_narrow(const __half* A, const __half* W,
                       const float* bias, const float* res,
                       float* C, __half* Cf, int N, int K, int flags) {
    dim3 g(BT / 64, (N + 63) / 64);
    gemm_n64<<<g, 256, GEMM_SMEM_N>>>(A, W, bias, res, C, Cf, N, K, flags);
}

extern "C" void kernel_launch(void* const* d_in, const int* in_sizes, int n_in,
                              void* d_out, int out_size) {
    const int*   input_ids = (const int*)  d_in[0];
    const float* tok_emb   = (const float*)d_in[1];
    const float* pos_emb   = (const float*)d_in[2];
    const float* ln1_scale = (const float*)d_in[3];
    const float* ln1_bias  = (const float*)d_in[4];
    const float* qkv_w     = (const float*)d_in[5];
    const float* out_w     = (const float*)d_in[6];
    const float* ln2_scale = (const float*)d_in[7];
    const float* ln2_bias  = (const float*)d_in[8];
    const float* fc1_w     = (const float*)d_in[9];
    const float* fc1_b     = (const float*)d_in[10];
    const float* fc2_w     = (const float*)d_in[11];
    const float* fc2_b     = (const float*)d_in[12];
    const float* lnf_scale = (const float*)d_in[13];
    const float* lnf_bias  = (const float*)d_in[14];
    float* logits = (float*)d_out;

    cudaFuncSetAttribute((const void*)gemm_wide, cudaFuncAttributeMaxDynamicSharedMemorySize, GEMM_SMEM_W);
    cudaFuncSetAttribute((const void*)gemm_n64,  cudaFuncAttributeMaxDynamicSharedMemorySize, GEMM_SMEM_N);

    float *x;
    __half *qkvh, *h, *at, *f, *qw, *ow, *f1, *f2, *te;
    cudaGetSymbolAddress((void**)&x,    g_x);
    cudaGetSymbolAddress((void**)&qkvh, g_qkvh);
    cudaGetSymbolAddress((void**)&h,    g_h);
    cudaGetSymbolAddress((void**)&at,   g_at);
    cudaGetSymbolAddress((void**)&f,    g_f);
    cudaGetSymbolAddress((void**)&qw,   g_qw);  cudaGetSymbolAddress((void**)&ow,  g_ow);
    cudaGetSymbolAddress((void**)&f1,   g_f1);  cudaGetSymbolAddress((void**)&f2,  g_f2);
    cudaGetSymbolAddress((void**)&te,   g_te);

    conv_all_kernel<<<(C_TOT + 255) / 256, 256>>>(qkv_w, out_w, fc1_w, fc2_w, tok_emb,
                                                  qw, ow, f1, f2, te);

    embed_kernel<<<(BT * Ee + 255) / 256, 256>>>(input_ids, tok_emb, pos_emb, x);

    for (int l = 0; l < Ll; l++) {
        // attention block (pre-norm)
        ln_kernel<<<BT, 256>>>(x, ln1_scale + l * Ee, ln1_bias + l * Ee, h);
        run_wide(h, qw + (size_t)l * 3 * Ee * Ee,
                 nullptr, nullptr, nullptr, qkvh, 3 * Ee, Ee, FLAG_F16OUT);
        attn_tc<<<dim3(Tt/64, NHh, Bb), 128>>>(qkvh, at);
        run_narrow(at, ow + (size_t)l * Ee * Ee,
                   nullptr, x, x, nullptr, Ee, Ee, FLAG_RES);
        // FFN block (pre-norm)
        ln_kernel<<<BT, 256>>>(x, ln2_scale + l * Ee, ln2_bias + l * Ee, h);
        run_wide(h, f1 + (size_t)l * FFf * Ee,
                 fc1_b + (size_t)l * FFf, nullptr, nullptr, f,
                 FFf, Ee, FLAG_BIAS | FLAG_GELU | FLAG_F16OUT);
        run_narrow(f, f2 + (size_t)l * Ee * FFf,
                   fc2_b + (size_t)l * Ee, x, x, nullptr,
                   Ee, FFf, FLAG_BIAS | FLAG_RES);
    }

    // final layernorm + tied LM head
    ln_kernel<<<BT, 256>>>(x, lnf_scale, lnf_bias, h);
    run_wide(h, te, nullptr, nullptr, logits, nullptr, Vv, Ee, 0);
}

// round 17
// speedup vs baseline: 2.9455x; 1.0481x over previous
#include <cuda_runtime.h>
#include <cuda_bf16.h>
#include <cuda_fp16.h>
#include <cstdint>
#include <math.h>

// ---------------- problem constants ----------------
#define Vv 50257
#define Ee 768
#define NHh 12
#define HDd 64
#define Ll 4
#define Tt 1024
#define Bb 2
#define FFf 3072
#define BT (Bb*Tt)            // 2048 rows

// ---------------- scratch (static, no allocs) ----------------
__device__ float g_x  [BT * Ee];                 // residual stream (fp32)
__device__ __half g_qkvh[BT * 3*Ee];             // qkv projection (fp16)
__device__ __half g_h [BT*Ee];                   // LN output fp16
__device__ __half g_at[BT*Ee];                   // attn output fp16
__device__ __half g_f [BT*FFf];                  // ffn hidden fp16
// weights, single fp16
__device__ __half g_qw[Ll*3*Ee*Ee];
__device__ __half g_ow[Ll*Ee*Ee];
__device__ __half g_f1[Ll*FFf*Ee];
__device__ __half g_f2[Ll*Ee*FFf];
__device__ __half g_te[Vv*Ee];

__device__ __forceinline__ uint32_t smem_u32(const void* p) {
    uint32_t a;
    asm("{ .reg .u64 t; cvta.to.shared.u64 t, %1; cvt.u32.u64 %0, t; }" : "=r"(a) : "l"(p));
    return a;
}
__device__ __forceinline__ void cp16(uint32_t dst, const void* src) {
    asm volatile("cp.async.cg.shared.global [%0], [%1], 16;" :: "r"(dst), "l"(src));
}
#define CP_COMMIT() asm volatile("cp.async.commit_group;" ::: "memory")
template<int N> __device__ __forceinline__ void cp_wait() {
    asm volatile("cp.async.wait_group %0;" :: "n"(N) : "memory");
}

__device__ __forceinline__ void ldsm_x4(uint32_t a, uint32_t& r0, uint32_t& r1, uint32_t& r2, uint32_t& r3) {
    asm volatile("ldmatrix.sync.aligned.m8n8.x4.shared.b16 {%0,%1,%2,%3}, [%4];"
                 : "=r"(r0), "=r"(r1), "=r"(r2), "=r"(r3) : "r"(a));
}
__device__ __forceinline__ void ldsm_x4t(uint32_t a, uint32_t& r0, uint32_t& r1, uint32_t& r2, uint32_t& r3) {
    asm volatile("ldmatrix.sync.aligned.m8n8.x4.trans.shared.b16 {%0,%1,%2,%3}, [%4];"
                 : "=r"(r0), "=r"(r1), "=r"(r2), "=r"(r3) : "r"(a));
}
__device__ __forceinline__ void mma16816f(float* d, const uint32_t* a, const uint32_t* b) {
    asm volatile("mma.sync.aligned.m16n8k16.row.col.f32.f16.f16.f32 "
                 "{%0,%1,%2,%3}, {%4,%5,%6,%7}, {%8,%9}, {%0,%1,%2,%3};"
                 : "+f"(d[0]), "+f"(d[1]), "+f"(d[2]), "+f"(d[3])
                 : "r"(a[0]), "r"(a[1]), "r"(a[2]), "r"(a[3]), "r"(b[0]), "r"(b[1]));
}

// ---------------- merged fp32 -> fp16 weight conversion (one launch) ----------------
#define C_QW (Ll*3*Ee*Ee/4)
#define C_OW (Ll*Ee*Ee/4)
#define C_F1 (Ll*FFf*Ee/4)
#define C_F2 (Ll*Ee*FFf/4)
#define C_TE (Vv*Ee/4)
#define C_TOT (C_QW + C_OW + C_F1 + C_F2 + C_TE)

__global__ void conv_all_kernel(const float* __restrict__ qkv_w, const float* __restrict__ out_w,
                                const float* __restrict__ fc1_w, const float* __restrict__ fc2_w,
                                const float* __restrict__ tok_emb,
                                __half* __restrict__ qw, __half* __restrict__ ow,
                                __half* __restrict__ f1, __half* __restrict__ f2,
                                __half* __restrict__ te) {
    int i = blockIdx.x * blockDim.x + threadIdx.x;
    if (i >= C_TOT) return;
    const float* src; __half* dst; int off = i;
    if (off < C_QW)                        { src = qkv_w;  dst = qw; }
    else if ((off -= C_QW) < C_OW)         { src = out_w;  dst = ow; }
    else if ((off -= C_OW) < C_F1)         { src = fc1_w;  dst = f1; }
    else if ((off -= C_F1) < C_F2)         { src = fc2_w;  dst = f2; }
    else      { off -= C_F2;                 src = tok_emb; dst = te; }
    float4 v = ((const float4*)src)[off];
    __half2 a, b;
    a.x = __float2half(v.x); a.y = __float2half(v.y);
    b.x = __float2half(v.z); b.y = __float2half(v.w);
    ((__half2*)dst)[2*off]   = a;
    ((__half2*)dst)[2*off+1] = b;
}

// ---------------- embedding ----------------
__global__ void embed_kernel(const int* __restrict__ ids, const float* __restrict__ tok,
                             const float* __restrict__ pos, float* __restrict__ out) {
    int i = blockIdx.x * blockDim.x + threadIdx.x;
    if (i >= BT * Ee) return;
    int e = i % Ee, row = i / Ee, t = row % Tt;
    out[i] = tok[(size_t)ids[row] * Ee + e] + pos[t * Ee + e];
}

// ---------------- layernorm -> fp16 ----------------
__global__ void ln_kernel(const float* __restrict__ x,
                          const float* __restrict__ scale, const float* __restrict__ bias,
                          __half* __restrict__ o) {
    __shared__ float s1[256], s2[256];
    int row = blockIdx.x, tid = threadIdx.x;
    const float* xr = x + (size_t)row * Ee;
    float sum = 0.f, sq = 0.f;
    for (int c = tid; c < Ee; c += 256) { float v = xr[c]; sum += v; sq += v * v; }
    s1[tid] = sum; s2[tid] = sq; __syncthreads();
    for (int s = 128; s > 0; s >>= 1) {
        if (tid < s) { s1[tid] += s1[tid+s]; s2[tid] += s2[tid+s]; }
        __syncthreads();
    }
    float mean = s1[0] * (1.0f / Ee);
    float var  = s2[0] * (1.0f / Ee) - mean * mean;
    float rstd = rsqrtf(var + 1e-5f);
    for (int c = tid; c < Ee; c += 256) {
        float v = (xr[c] - mean) * rstd * scale[c] + bias[c];
        o[(size_t)row * Ee + c] = __float2half(v);
    }
}

// ---------------- HMMA GEMM flags ----------------
#define FLAG_BIAS 1
#define FLAG_GELU 2
#define FLAG_RES  4
#define FLAG_F16OUT 8

__device__ __forceinline__ void epi_store(float v0, float v1, int row, int col, int N,
                                          const float* bias, const float* res,
                                          float* C, __half* Cf, int flags) {
    if (flags & FLAG_BIAS) {
        if (col < N)     v0 += bias[col];
        if (col + 1 < N) v1 += bias[col + 1];
    }
    if (flags & FLAG_GELU) {
        v0 = 0.5f * v0 * (1.0f + erff(v0 * 0.7071067811865476f));
        v1 = 0.5f * v1 * (1.0f + erff(v1 * 0.7071067811865476f));
    }
    size_t ci = (size_t)row * N + col;
    if (flags & FLAG_RES) {
        if (col < N)     v0 += res[ci];
        if (col + 1 < N) v1 += res[ci + 1];
    }
    if (flags & FLAG_F16OUT) {
        // col always even; F16OUT targets have even N => packed 4B store is aligned & in-bounds
        if (col + 1 < N) {
            *(__half2*)(Cf + ci) = __floats2half2_rn(v0, v1);
        } else if (col < N) {
            Cf[ci] = __float2half(v0);
        }
    } else {
        if (col < N)     C[ci]   = v0;
        if (col + 1 < N) C[ci+1] = v1;
    }
}

// BK=64: 128B rows, per-row XOR-16B swizzle (chunk ^ (row&7)); conflict-free ldsm.
#define SWZ(row, chunk) (((uint32_t)(row)) * 128u + ((uint32_t)((chunk) ^ ((row) & 7)) << 4))

// ======== WIDE: BM=128, BN=128, BK=64, 3 stages, 2 CTAs/SM ========
#define NSTAGE_W 3
#define A_TILE_W (128 * 128)    // 16384
#define STAGE_W  (2 * A_TILE_W) // 32768
#define GEMM_SMEM_W (NSTAGE_W * STAGE_W)   // 98304

__global__ __launch_bounds__(256, 2)
void gemm_wide(const __half* __restrict__ A, const __half* __restrict__ W,
               const float* __restrict__ bias, const float* __restrict__ res,
               float* __restrict__ C, __half* __restrict__ Cf,
               int N, int K, int flags) {
    extern __shared__ char smem[];
    const uint32_t sb = smem_u32(smem);
    const int tid  = threadIdx.x;
    const int lane = tid & 31;
    const int wid  = tid >> 5;
    const int wm   = wid >> 2;
    const int wn   = wid & 3;
    const int bm   = blockIdx.x * 128;
    const int bn   = blockIdx.y * 128;

    float acc[4][4][4];
    #pragma unroll
    for (int i = 0; i < 4; i++)
        #pragma unroll
        for (int j = 0; j < 4; j++)
            #pragma unroll
            for (int r = 0; r < 4; r++) acc[i][j][r] = 0.f;

    const int nc = K >> 6;   // BK = 64

    auto load_stage = [&](int c, int stage) {
        const int k0 = c << 6;
        const uint32_t sdst = sb + stage * STAGE_W;
        #pragma unroll
        for (int it = 0; it < 8; it++) {
            int gi = it * 256 + tid;
            uint32_t dst; const __half* src;
            if (gi < 1024) {
                int row = gi >> 3, chunk = gi & 7;
                dst = sdst + SWZ(row, chunk);
                src = A + (size_t)(bm + row) * K + k0 + chunk * 8;
            } else {
                int li = gi - 1024;
                int row = li >> 3, chunk = li & 7;
                int gn = bn + row; if (gn > N - 1) gn = N - 1;
                dst = sdst + A_TILE_W + SWZ(row, chunk);
                src = W + (size_t)gn * K + k0 + chunk * 8;
            }
            cp16(dst, src);
        }
    };

    #pragma unroll
    for (int s = 0; s < NSTAGE_W - 1; s++) {
        if (s < nc) load_stage(s, s);
        CP_COMMIT();
    }

    for (int c = 0; c < nc; c++) {
        cp_wait<NSTAGE_W - 2>();
        __syncthreads();

        if (c + NSTAGE_W - 1 < nc) load_stage(c + NSTAGE_W - 1, (c + NSTAGE_W - 1) % NSTAGE_W);
        CP_COMMIT();

        const uint32_t st = sb + (c % NSTAGE_W) * STAGE_W;
        #pragma unroll
        for (int ks = 0; ks < 4; ks++) {
            uint32_t fa[4][4], fb[4][2];
            #pragma unroll
            for (int p = 0; p < 2; p++) {
                int nrow = wn * 32 + p * 16 + (lane & 7) + 8 * (lane >> 4);
                int chunk = ks * 2 + ((lane >> 3) & 1);
                uint32_t r0,r1,r2,r3;
                ldsm_x4(st + A_TILE_W + SWZ(nrow, chunk), r0, r1, r2, r3);
                fb[2*p][0]=r0; fb[2*p][1]=r1; fb[2*p+1][0]=r2; fb[2*p+1][1]=r3;
            }
            #pragma unroll
            for (int i = 0; i < 4; i++) {
                int mrow = wm * 64 + i * 16 + (lane & 7) + 8 * ((lane >> 3) & 1);
                int chunk = ks * 2 + (lane >> 4);
                ldsm_x4(st + SWZ(mrow, chunk), fa[i][0], fa[i][1], fa[i][2], fa[i][3]);
            }
            #pragma unroll
            for (int i = 0; i < 4; i++)
                #pragma unroll
                for (int j = 0; j < 4; j++)
                    mma16816f(acc[i][j], fa[i], fb[j]);
        }
    }

    #pragma unroll
    for (int i = 0; i < 4; i++) {
        int row0 = bm + wm * 64 + i * 16 + (lane >> 2);
        #pragma unroll
        for (int j = 0; j < 4; j++) {
            int col = bn + wn * 32 + j * 8 + (lane & 3) * 2;
            #pragma unroll
            for (int half = 0; half < 2; half++)
                epi_store(acc[i][j][2*half], acc[i][j][2*half+1],
                          row0 + half * 8, col, N, bias, res, C, Cf, flags);
        }
    }
}

// ======== NARROW: BM=64, BN=64, BK=64, 4 stages, 3 CTAs/SM ========
#define NSTAGE_N 4
#define A_TILE_N (64 * 128)     // 8192
#define STAGE_N  (2 * A_TILE_N) // 16384
#define GEMM_SMEM_N (NSTAGE_N * STAGE_N)   // 65536

__global__ __launch_bounds__(256, 3)
void gemm_n64(const __half* __restrict__ A, const __half* __restrict__ W,
              const float* __restrict__ bias, const float* __restrict__ res,
              float* __restrict__ C, __half* __restrict__ Cf,
              int N, int K, int flags) {
    extern __shared__ char smem[];
    const uint32_t sb = smem_u32(smem);
    const int tid  = threadIdx.x;
    const int lane = tid & 31;
    const int wid  = tid >> 5;
    const int wm   = wid >> 2;
    const int wn   = wid & 3;
    const int bm   = blockIdx.x * 64;
    const int bn   = blockIdx.y * 64;

    float acc[2][2][4];
    #pragma unroll
    for (int i = 0; i < 2; i++)
        #pragma unroll
        for (int j = 0; j < 2; j++)
            #pragma unroll
            for (int r = 0; r < 4; r++) acc[i][j][r] = 0.f;

    const int nc = K >> 6;

    auto load_stage = [&](int c, int stage) {
        const int k0 = c << 6;
        const uint32_t sdst = sb + stage * STAGE_N;
        #pragma unroll
        for (int it = 0; it < 4; it++) {
            int gi = it * 256 + tid;
            uint32_t dst; const __half* src;
            if (gi < 512) {
                int row = gi >> 3, chunk = gi & 7;
                dst = sdst + SWZ(row, chunk);
                src = A + (size_t)(bm + row) * K + k0 + chunk * 8;
            } else {
                int li = gi - 512;
                int row = li >> 3, chunk = li & 7;
                int gn = bn + row; if (gn > N - 1) gn = N - 1;
                dst = sdst + A_TILE_N + SWZ(row, chunk);
                src = W + (size_t)gn * K + k0 + chunk * 8;
            }
            cp16(dst, src);
        }
    };

    #pragma unroll
    for (int s = 0; s < NSTAGE_N - 1; s++) {
        if (s < nc) load_stage(s, s);
        CP_COMMIT();
    }

    for (int c = 0; c < nc; c++) {
        cp_wait<NSTAGE_N - 2>();
        __syncthreads();

        if (c + NSTAGE_N - 1 < nc) load_stage(c + NSTAGE_N - 1, (c + NSTAGE_N - 1) % NSTAGE_N);
        CP_COMMIT();

        const uint32_t st = sb + (c % NSTAGE_N) * STAGE_N;
        #pragma unroll
        for (int ks = 0; ks < 4; ks++) {
            uint32_t fa[2][4], fb[2][2];
            {
                int nrow = wn * 16 + (lane & 7) + 8 * (lane >> 4);
                int chunk = ks * 2 + ((lane >> 3) & 1);
                uint32_t r0,r1,r2,r3;
                ldsm_x4(st + A_TILE_N + SWZ(nrow, chunk), r0, r1, r2, r3);
                fb[0][0]=r0; fb[0][1]=r1; fb[1][0]=r2; fb[1][1]=r3;
            }
            #pragma unroll
            for (int i = 0; i < 2; i++) {
                int mrow = wm * 32 + i * 16 + (lane & 7) + 8 * ((lane >> 3) & 1);
                int chunk = ks * 2 + (lane >> 4);
                ldsm_x4(st + SWZ(mrow, chunk), fa[i][0], fa[i][1], fa[i][2], fa[i][3]);
            }
            #pragma unroll
            for (int i = 0; i < 2; i++)
                #pragma unroll
                for (int j = 0; j < 2; j++)
                    mma16816f(acc[i][j], fa[i], fb[j]);
        }
    }

    #pragma unroll
    for (int i = 0; i < 2; i++) {
        int row0 = bm + wm * 32 + i * 16 + (lane >> 2);
        #pragma unroll
        for (int j = 0; j < 2; j++) {
            int col = bn + wn * 16 + j * 8 + (lane & 3) * 2;
            #pragma unroll
            for (int half = 0; half < 2; half++)
                epi_store(acc[i][j][2*half], acc[i][j][2*half+1],
                          row0 + half * 8, col, N, bias, res, C, Cf, flags);
        }
    }
}

// ---------------- tensor-core flash attention (K/V double-buffered) ----------------
// grid (T/64, NH, B), 128 threads (4 warps, each owns 16 q rows).
__global__ __launch_bounds__(128)
void attn_tc(const __half* __restrict__ qkv, __half* __restrict__ o) {
    __shared__ __half Qs[64 * 64], Ks[2][64 * 64], Vs[2][64 * 64];
    const int qt = blockIdx.x, h = blockIdx.y, b = blockIdx.z;
    const int tid = threadIdx.x;
    const int lane = tid & 31;
    const int w = tid >> 5;
    const uint32_t qb = smem_u32(Qs);

    auto load_kv = [&](int kt, int stage) {
        const uint32_t kb = smem_u32(Ks[stage]);
        const uint32_t vbp = smem_u32(Vs[stage]);
        for (int i = tid; i < 512; i += 128) {
            int r = i >> 3, ch = i & 7;
            size_t base = ((size_t)(b * Tt + kt * 64 + r)) * (3 * Ee) + h * HDd;
            cp16(kb + SWZ(r, ch), qkv + base + Ee + ch * 8);
            cp16(vbp + SWZ(r, ch), qkv + base + 2 * Ee + ch * 8);
        }
    };

    // load Q tile + first K/V stage
    for (int i = tid; i < 512; i += 128) {
        int r = i >> 3, ch = i & 7;
        cp16(qb + SWZ(r, ch),
             qkv + ((size_t)(b * Tt + qt * 64 + r)) * (3 * Ee) + h * HDd + ch * 8);
    }
    load_kv(0, 0);
    CP_COMMIT();

    float m_run[2] = {-1e30f, -1e30f}, l_run[2] = {0.f, 0.f};
    float oacc[8][4];
    #pragma unroll
    for (int t = 0; t < 8; t++)
        #pragma unroll
        for (int r = 0; r < 4; r++) oacc[t][r] = 0.f;

    const int rowA = qt * 64 + w * 16 + (lane >> 2);   // global q row (and rowA+8)

    for (int kt = 0; kt <= qt; kt++) {
        // prefetch next K/V while waiting on current
        if (kt + 1 <= qt) { load_kv(kt + 1, (kt + 1) & 1); CP_COMMIT(); cp_wait<1>(); }
        else              { cp_wait<0>(); }
        __syncthreads();

        const uint32_t kb = smem_u32(Ks[kt & 1]);
        const uint32_t vbp = smem_u32(Vs[kt & 1]);

        // ---- S = Q @ K^T (fp32 acc) ----
        float sacc[8][4];
        #pragma unroll
        for (int t = 0; t < 8; t++)
            #pragma unroll
            for (int r = 0; r < 4; r++) sacc[t][r] = 0.f;
        #pragma unroll
        for (int ks = 0; ks < 4; ks++) {
            uint32_t fa[4], fb[8][2];
            {
                int mrow = w * 16 + (lane & 7) + 8 * ((lane >> 3) & 1);
                int chunk = ks * 2 + (lane >> 4);
                ldsm_x4(qb + SWZ(mrow, chunk), fa[0], fa[1], fa[2], fa[3]);
            }
            #pragma unroll
            for (int p = 0; p < 4; p++) {
                int nrow = p * 16 + (lane & 7) + 8 * (lane >> 4);
                int chunk = ks * 2 + ((lane >> 3) & 1);
                uint32_t r0,r1,r2,r3;
                ldsm_x4(kb + SWZ(nrow, chunk), r0, r1, r2, r3);
                fb[2*p][0]=r0; fb[2*p][1]=r1; fb[2*p+1][0]=r2; fb[2*p+1][1]=r3;
            }
            #pragma unroll
            for (int t = 0; t < 8; t++)
                mma16816f(sacc[t], fa, fb[t]);
        }

        // ---- scale + causal mask ----
        #pragma unroll
        for (int t = 0; t < 8; t++) {
            int colg = kt * 64 + t * 8 + (lane & 3) * 2;
            #pragma unroll
            for (int r = 0; r < 4; r++) sacc[t][r] *= 0.125f;
            if (kt == qt) {
                if (colg     > rowA)     sacc[t][0] = -1e30f;
                if (colg + 1 > rowA)     sacc[t][1] = -1e30f;
                if (colg     > rowA + 8) sacc[t][2] = -1e30f;
                if (colg + 1 > rowA + 8) sacc[t][3] = -1e30f;
            }
        }

        // ---- online softmax (rows rowA, rowA+8) ----
        float mA = -1e30f, mB = -1e30f;
        #pragma unroll
        for (int t = 0; t < 8; t++) {
            mA = fmaxf(mA, fmaxf(sacc[t][0], sacc[t][1]));
            mB = fmaxf(mB, fmaxf(sacc[t][2], sacc[t][3]));
        }
        mA = fmaxf(mA, __shfl_xor_sync(0xFFFFFFFFu, mA, 1));
        mA = fmaxf(mA, __shfl_xor_sync(0xFFFFFFFFu, mA, 2));
        mB = fmaxf(mB, __shfl_xor_sync(0xFFFFFFFFu, mB, 1));
        mB = fmaxf(mB, __shfl_xor_sync(0xFFFFFFFFu, mB, 2));
        float mnA = fmaxf(m_run[0], mA), mnB = fmaxf(m_run[1], mB);
        float fA = __expf(m_run[0] - mnA), fB = __expf(m_run[1] - mnB);
        float psA = 0.f, psB = 0.f;
        #pragma unroll
        for (int t = 0; t < 8; t++) {
            sacc[t][0] = __expf(sacc[t][0] - mnA);
            sacc[t][1] = __expf(sacc[t][1] - mnA);
            sacc[t][2] = __expf(sacc[t][2] - mnB);
            sacc[t][3] = __expf(sacc[t][3] - mnB);
            psA += sacc[t][0] + sacc[t][1];
            psB += sacc[t][2] + sacc[t][3];
        }
        psA += __shfl_xor_sync(0xFFFFFFFFu, psA, 1);
        psA += __shfl_xor_sync(0xFFFFFFFFu, psA, 2);
        psB += __shfl_xor_sync(0xFFFFFFFFu, psB, 1);
        psB += __shfl_xor_sync(0xFFFFFFFFu, psB, 2);
        l_run[0] = l_run[0] * fA + psA;
        l_run[1] = l_run[1] * fB + psB;
        m_run[0] = mnA; m_run[1] = mnB;
        #pragma unroll
        for (int t = 0; t < 8; t++) {
            oacc[t][0] *= fA; oacc[t][1] *= fA;
            oacc[t][2] *= fB; oacc[t][3] *= fB;
        }

        // ---- O += P @ V (P from registers; V via ldsm.trans) ----
        #pragma unroll
        for (int ks = 0; ks < 4; ks++) {
            uint32_t pa[4];
            {
                __half2 h0 = __floats2half2_rn(sacc[2*ks][0],   sacc[2*ks][1]);
                __half2 h1 = __floats2half2_rn(sacc[2*ks][2],   sacc[2*ks][3]);
                __half2 h2 = __floats2half2_rn(sacc[2*ks+1][0], sacc[2*ks+1][1]);
                __half2 h3 = __floats2half2_rn(sacc[2*ks+1][2], sacc[2*ks+1][3]);
                pa[0] = *(uint32_t*)&h0; pa[1] = *(uint32_t*)&h1;
                pa[2] = *(uint32_t*)&h2; pa[3] = *(uint32_t*)&h3;
            }
            #pragma unroll
            for (int dp = 0; dp < 4; dp++) {
                int vrow = ks * 16 + (lane & 7) + 8 * ((lane >> 3) & 1);
                int chunk = 2 * dp + (lane >> 4);
                uint32_t r0,r1,r2,r3;
                ldsm_x4t(vbp + SWZ(vrow, chunk), r0, r1, r2, r3);
                uint32_t b0[2] = {r0, r1}, b1[2] = {r2, r3};
                mma16816f(oacc[2*dp],     pa, b0);
                mma16816f(oacc[2*dp + 1], pa, b1);
            }
        }
        __syncthreads();
    }

    float invA = 1.0f / l_run[0], invB = 1.0f / l_run[1];
    size_t baseA = ((size_t)(b * Tt + rowA)) * Ee + h * HDd;
    size_t baseB = ((size_t)(b * Tt + rowA + 8)) * Ee + h * HDd;
    #pragma unroll
    for (int t = 0; t < 8; t++) {
        int col = t * 8 + (lane & 3) * 2;
        __half2 va = __floats2half2_rn(oacc[t][0] * invA, oacc[t][1] * invA);
        __half2 vb2 = __floats2half2_rn(oacc[t][2] * invB, oacc[t][3] * invB);
        *(__half2*)(o + baseA + col) = va;
        *(__half2*)(o + baseB + col) = vb2;
    }
}

// ---------------- launcher ----------------
static void run_wide(const __half* A, const __half* W,
                     const float* bias, const float* res,
                     float* C, __half* Cf, int N, int K, int flags) {
    dim3 g(BT / 128, (N + 127) / 128);
    gemm_wide<<<g, 256, GEMM_SMEM_W>>>(A, W, bias, res, C, Cf, N, K, flags);
}
static void run_narrow(const __half* A, const __half* W,
                       const float* bias, const float* res,
                       float* C, __half* Cf, int N, int K, int flags) {
    dim3 g(BT / 64, (N + 63) / 64);
    gemm_n64<<<g, 256, GEMM_SMEM_N>>>(A, W, bias, res, C, Cf, N, K, flags);
}

extern "C" void kernel_launch(void* const* d_in, const int* in_sizes, int n_in,
                              void* d_out, int out_size) {
    const int*   input_ids = (const int*)  d_in[0];
    const float* tok_emb   = (const float*)d_in[1];
    const float* pos_emb   = (const float*)d_in[2];
    const float* ln1_scale = (const float*)d_in[3];
    const float* ln1_bias  = (const float*)d_in[4];
    const float* qkv_w     = (const float*)d_in[5];
    const float* out_w     = (const float*)d_in[6];
    const float* ln2_scale = (const float*)d_in[7];
    const float* ln2_bias  = (const float*)d_in[8];
    const float* fc1_w     = (const float*)d_in[9];
    const float* fc1_b     = (const float*)d_in[10];
    const float* fc2_w     = (const float*)d_in[11];
    const float* fc2_b     = (const float*)d_in[12];
    const float* lnf_scale = (const float*)d_in[13];
    const float* lnf_bias  = (const float*)d_in[14];
    float* logits = (float*)d_out;

    cudaFuncSetAttribute((const void*)gemm_wide, cudaFuncAttributeMaxDynamicSharedMemorySize, GEMM_SMEM_W);
    cudaFuncSetAttribute((const void*)gemm_n64,  cudaFuncAttributeMaxDynamicSharedMemorySize, GEMM_SMEM_N);

    float *x;
    __half *qkvh, *h, *at, *f, *qw, *ow, *f1, *f2, *te;
    cudaGetSymbolAddress((void**)&x,    g_x);
    cudaGetSymbolAddress((void**)&qkvh, g_qkvh);
    cudaGetSymbolAddress((void**)&h,    g_h);
    cudaGetSymbolAddress((void**)&at,   g_at);
    cudaGetSymbolAddress((void**)&f,    g_f);
    cudaGetSymbolAddress((void**)&qw,   g_qw);  cudaGetSymbolAddress((void**)&ow,  g_ow);
    cudaGetSymbolAddress((void**)&f1,   g_f1);  cudaGetSymbolAddress((void**)&f2,  g_f2);
    cudaGetSymbolAddress((void**)&te,   g_te);

    conv_all_kernel<<<(C_TOT + 255) / 256, 256>>>(qkv_w, out_w, fc1_w, fc2_w, tok_emb,
                                                  qw, ow, f1, f2, te);

    embed_kernel<<<(BT * Ee + 255) / 256, 256>>>(input_ids, tok_emb, pos_emb, x);

    for (int l = 0; l < Ll; l++) {
        // attention block (pre-norm)
        ln_kernel<<<BT, 256>>>(x, ln1_scale + l * Ee, ln1_bias + l * Ee, h);
        run_wide(h, qw + (size_t)l * 3 * Ee * Ee,
                 nullptr, nullptr, nullptr, qkvh, 3 * Ee, Ee, FLAG_F16OUT);
        attn_tc<<<dim3(Tt/64, NHh, Bb), 128>>>(qkvh, at);
        run_narrow(at, ow + (size_t)l * Ee * Ee,
                   nullptr, x, x, nullptr, Ee, Ee, FLAG_RES);
        // FFN block (pre-norm)
        ln_kernel<<<BT, 256>>>(x, ln2_scale + l * Ee, ln2_bias + l * Ee, h);
        run_wide(h, f1 + (size_t)l * FFf * Ee,
                 fc1_b + (size_t)l * FFf, nullptr, nullptr, f,
                 FFf, Ee, FLAG_BIAS | FLAG_GELU | FLAG_F16OUT);
        run_narrow(f, f2 + (size_t)l * Ee * FFf,
                   fc2_b + (size_t)l * Ee, x, x, nullptr,
                   Ee, FFf, FLAG_BIAS | FLAG_RES);
    }

    // final layernorm + tied LM head
    ln_kernel<<<BT, 256>>>(x, lnf_scale, lnf_bias, h);
    run_wide(h, te, nullptr, nullptr, logits, nullptr, Vv, Ee, 0);
}